// round 3
// baseline (speedup 1.0000x reference)
#include <cuda_runtime.h>

#define BB 4096
#define DD 64
#define HH8 8
#define CC 16384
#define TAU 0.3f
#define NEG (-1e30f)

// ---- scratch offsets (floats) ----
constexpr int OFF_AT    = 0;
constexpr int OFF_APART = OFF_AT    + 4096;
constexpr int OFF_KN    = OFF_APART + 32768;
constexpr int OFF_Q     = OFF_KN    + 1048576;
constexpr int OFF_VMEM  = OFF_Q     + 262144;
constexpr int OFF_VC    = OFF_VMEM  + 262144;
constexpr int OFF_PVAL  = OFF_VC    + 262144;   // 4096*16*4
constexpr int OFF_PIDX  = OFF_PVAL  + 262144;
constexpr int OFF_X     = OFF_PIDX  + 262144;
constexpr int OFF_GI    = OFF_X     + 524288;
constexpr int OFF_GH    = OFF_GI    + 1572864;
constexpr int OFF_H2A   = OFF_GH    + 1572864;
constexpr int OFF_H2B   = OFF_H2A   + 524288;
constexpr int OFF_HID   = OFF_H2B   + 524288;
constexpr int OFF_Z1    = OFF_HID   + 524288;
constexpr int OFF_Z2    = OFF_Z1    + 262144;
constexpr int OFF_GH0   = OFF_Z2    + 262144;   // 512
constexpr int OFF_CFP   = OFF_GH0   + 512;      // 256
constexpr int OFF_ZERO  = OFF_CFP   + 256;      // 512 zeros
constexpr int SCR_TOTAL = OFF_ZERO  + 512;

__device__ float d_scr[SCR_TOTAL];

#define BETTER(v,id,V,I) ((v) > (V) || ((v) == (V) && (id) < (I)))

__device__ __forceinline__ void ins4(float (&tv)[4], int (&ti)[4], float v, int id) {
    if (BETTER(v, id, tv[3], ti[3])) {
        if (BETTER(v, id, tv[0], ti[0])) {
            tv[3]=tv[2]; ti[3]=ti[2]; tv[2]=tv[1]; ti[2]=ti[1];
            tv[1]=tv[0]; ti[1]=ti[0]; tv[0]=v; ti[0]=id;
        } else if (BETTER(v, id, tv[1], ti[1])) {
            tv[3]=tv[2]; ti[3]=ti[2]; tv[2]=tv[1]; ti[2]=ti[1];
            tv[1]=v; ti[1]=id;
        } else if (BETTER(v, id, tv[2], ti[2])) {
            tv[3]=tv[2]; ti[3]=ti[2]; tv[2]=v; ti[2]=id;
        } else {
            tv[3]=v; ti[3]=id;
        }
    }
}

// ---- prep: Apart[h] = Wk_h^T @ (mem_h @ Wo^T) ----
__global__ void prepA_kernel(const float* __restrict__ mem,
                             const float* __restrict__ Wk,
                             const float* __restrict__ Wo,
                             float* __restrict__ Apart)
{
    int h = blockIdx.x;
    __shared__ float WoT[64 * 65];
    __shared__ float Mh[64 * 64];
    int t = threadIdx.x;
    #pragma unroll
    for (int p = 0; p < 16; p++) {
        int e = t + p * 256;
        int r = e >> 6, c = e & 63;
        WoT[c * 65 + r] = Wo[e];
    }
    __syncthreads();
    #pragma unroll
    for (int p = 0; p < 16; p++) {
        int e = t + p * 256;
        int dp = e >> 6, j = e & 63;
        const float* mrow = mem + h * 4096 + dp * 64;
        float s = 0.f;
        #pragma unroll
        for (int ee = 0; ee < 64; ee++) s += mrow[ee] * WoT[ee * 65 + j];
        Mh[dp * 64 + j] = s;
    }
    __syncthreads();
    #pragma unroll
    for (int p = 0; p < 16; p++) {
        int e = t + p * 256;
        int i = e >> 6, j = e & 63;
        float s = 0.f;
        #pragma unroll
        for (int dp = 0; dp < 64; dp++)
            s += Wk[(h * 64 + dp) * 64 + i] * Mh[dp * 64 + j];
        Apart[h * 4096 + e] = s;
    }
}

__global__ void reduceAT_kernel(const float* __restrict__ Apart,
                                float* __restrict__ AT)
{
    int e = blockIdx.x * 256 + threadIdx.x;
    int i = e >> 6, j = e & 63;
    float s = 0.f;
    #pragma unroll
    for (int h = 0; h < HH8; h++) s += Apart[h * 4096 + e];
    AT[j * 64 + i] = s * 0.125f;
}

// ---- row-normalize cache keys ----
__global__ void normalize_rows_kernel(const float* __restrict__ src,
                                      float* __restrict__ dst)
{
    int row  = blockIdx.x * 8 + (threadIdx.x >> 5);
    int lane = threadIdx.x & 31;
    float a = src[row * 64 + lane];
    float b = src[row * 64 + 32 + lane];
    float ss = a * a + b * b;
    #pragma unroll
    for (int off = 16; off > 0; off >>= 1)
        ss += __shfl_xor_sync(0xffffffffu, ss, off);
    float inv = 1.0f / fmaxf(sqrtf(ss), 1e-8f);
    dst[row * 64 + lane]      = a * inv;
    dst[row * 64 + 32 + lane] = b * inv;
}

// ---- gh0 = h0 @ Whh^T + bhh (384-vector) ----
__global__ void gh0_kernel(const float* __restrict__ h0, const float* __restrict__ Whh,
                           const float* __restrict__ bhh, float* __restrict__ gh0)
{
    int w = blockIdx.x * 8 + (threadIdx.x >> 5);  // 0..383
    int lane = threadIdx.x & 31;
    const float* row = Whh + w * 128;
    float s = row[lane] * h0[lane] + row[lane + 32] * h0[lane + 32]
            + row[lane + 64] * h0[lane + 64] + row[lane + 96] * h0[lane + 96];
    #pragma unroll
    for (int off = 16; off > 0; off >>= 1)
        s += __shfl_xor_sync(0xffffffffu, s, off);
    if (lane == 0) gh0[w] = s + bhh[w];
}

__global__ void buildx_kernel(const float* __restrict__ zprev,
                              const float* __restrict__ aemb,
                              const int* __restrict__ actions, int t,
                              float* __restrict__ x)
{
    int i = blockIdx.x * 256 + threadIdx.x;
    int b = i >> 7, p = i & 127;
    if (p < 64) x[i] = zprev[b * 64 + p];
    else        x[i] = aemb[actions[b * 2 + t] * 64 + (p - 64)];
}

// gates for t=0: gh is a broadcast 384-vector, hprev is broadcast h0 (128-vector)
__global__ void gates0_kernel(const float* __restrict__ gi, const float* __restrict__ gh0,
                              const float* __restrict__ h0, float* __restrict__ h2)
{
    int i = blockIdx.x * 256 + threadIdx.x;
    int b = i >> 7, j = i & 127;
    const float* gib = gi + b * 384;
    float r = 1.0f / (1.0f + expf(-(gib[j] + gh0[j])));
    float u = 1.0f / (1.0f + expf(-(gib[128 + j] + gh0[128 + j])));
    float n = tanhf(gib[256 + j] + r * gh0[256 + j]);
    float h = h0[j];
    h2[i] = (1.0f - u) * n + u * h;
}

__global__ void gates_kernel(const float* __restrict__ gi, const float* __restrict__ gh,
                             const float* __restrict__ hprev, float* __restrict__ h2)
{
    int i = blockIdx.x * 256 + threadIdx.x;
    int b = i >> 7, j = i & 127;
    const float* gib = gi + b * 384;
    const float* ghb = gh + b * 384;
    float r = 1.0f / (1.0f + expf(-(gib[j] + ghb[j])));
    float u = 1.0f / (1.0f + expf(-(gib[128 + j] + ghb[128 + j])));
    float n = tanhf(gib[256 + j] + r * ghb[256 + j]);
    float h = hprev[i];
    h2[i] = (1.0f - u) * n + u * h;
}

// ---- tiled GEMM: C = act((A?P) @ W^T + bias); optional elementwise premul P ----
__global__ __launch_bounds__(256) void gemm_kernel(
    const float* __restrict__ A, const float* __restrict__ P,
    const float* __restrict__ W, const float* __restrict__ bias,
    float* __restrict__ Cm, int N, int K, int act)
{
    __shared__ float As[16 * 68];
    __shared__ float Ws[16 * 68];
    int tid = threadIdx.x;
    int tx = tid & 15, ty = tid >> 4;
    int m0 = blockIdx.x * 64, n0 = blockIdx.y * 64;
    float acc[16];
    #pragma unroll
    for (int q = 0; q < 16; q++) acc[q] = 0.f;
    int li = tid >> 2;
    int lj = (tid & 3) * 4;
    for (int kt = 0; kt < K; kt += 16) {
        float4 av = *(const float4*)(A + (size_t)(m0 + li) * K + kt + lj);
        if (P) {
            float4 pv = *(const float4*)(P + (size_t)(m0 + li) * K + kt + lj);
            av.x *= pv.x; av.y *= pv.y; av.z *= pv.z; av.w *= pv.w;
        }
        float4 wv = *(const float4*)(W + (size_t)(n0 + li) * K + kt + lj);
        As[(lj + 0) * 68 + li] = av.x; As[(lj + 1) * 68 + li] = av.y;
        As[(lj + 2) * 68 + li] = av.z; As[(lj + 3) * 68 + li] = av.w;
        Ws[(lj + 0) * 68 + li] = wv.x; Ws[(lj + 1) * 68 + li] = wv.y;
        Ws[(lj + 2) * 68 + li] = wv.z; Ws[(lj + 3) * 68 + li] = wv.w;
        __syncthreads();
        #pragma unroll
        for (int k = 0; k < 16; k++) {
            float4 a = *(const float4*)(As + k * 68 + ty * 4);
            float4 b = *(const float4*)(Ws + k * 68 + tx * 4);
            acc[0]+=a.x*b.x; acc[1]+=a.x*b.y; acc[2]+=a.x*b.z; acc[3]+=a.x*b.w;
            acc[4]+=a.y*b.x; acc[5]+=a.y*b.y; acc[6]+=a.y*b.z; acc[7]+=a.y*b.w;
            acc[8]+=a.z*b.x; acc[9]+=a.z*b.y; acc[10]+=a.z*b.z; acc[11]+=a.z*b.w;
            acc[12]+=a.w*b.x; acc[13]+=a.w*b.y; acc[14]+=a.w*b.z; acc[15]+=a.w*b.w;
        }
        __syncthreads();
    }
    float4 bs = *(const float4*)(bias + n0 + tx * 4);
    float bcol[4] = {bs.x, bs.y, bs.z, bs.w};
    #pragma unroll
    for (int rr = 0; rr < 4; rr++) {
        int m = m0 + ty * 4 + rr;
        float4 o;
        float* op = (float*)&o;
        #pragma unroll
        for (int cc = 0; cc < 4; cc++) {
            float v = acc[rr * 4 + cc] + bcol[cc];
            if (act == 1) v = 0.5f * v * (1.0f + erff(v * 0.70710678118654752f));
            op[cc] = v;
        }
        *(float4*)(Cm + (size_t)m * N + n0 + tx * 4) = o;
    }
}

// ---- fused fusion+select: out = gap>TAU ? [z,vc]@Wf^T + bf : z ----
__global__ __launch_bounds__(256) void fuse2_kernel(
    const float* __restrict__ z, const float* __restrict__ vc,
    const float* __restrict__ Wf, const float* __restrict__ bf,
    const float* __restrict__ gap, float* __restrict__ out)
{
    __shared__ float As[16 * 68];
    __shared__ float Ws[16 * 68];
    int tid = threadIdx.x;
    int tx = tid & 15, ty = tid >> 4;
    int m0 = blockIdx.x * 64;
    float acc[16];
    #pragma unroll
    for (int q = 0; q < 16; q++) acc[q] = 0.f;
    int li = tid >> 2;
    int lj = (tid & 3) * 4;
    for (int kt = 0; kt < 128; kt += 16) {
        const float* src = (kt < 64) ? (z + (size_t)(m0 + li) * 64 + kt + lj)
                                     : (vc + (size_t)(m0 + li) * 64 + (kt - 64) + lj);
        float4 av = *(const float4*)src;
        float4 wv = *(const float4*)(Wf + (size_t)li * 128 + kt + lj);
        As[(lj + 0) * 68 + li] = av.x; As[(lj + 1) * 68 + li] = av.y;
        As[(lj + 2) * 68 + li] = av.z; As[(lj + 3) * 68 + li] = av.w;
        Ws[(lj + 0) * 68 + li] = wv.x; Ws[(lj + 1) * 68 + li] = wv.y;
        Ws[(lj + 2) * 68 + li] = wv.z; Ws[(lj + 3) * 68 + li] = wv.w;
        __syncthreads();
        #pragma unroll
        for (int k = 0; k < 16; k++) {
            float4 a = *(const float4*)(As + k * 68 + ty * 4);
            float4 b = *(const float4*)(Ws + k * 68 + tx * 4);
            acc[0]+=a.x*b.x; acc[1]+=a.x*b.y; acc[2]+=a.x*b.z; acc[3]+=a.x*b.w;
            acc[4]+=a.y*b.x; acc[5]+=a.y*b.y; acc[6]+=a.y*b.z; acc[7]+=a.y*b.w;
            acc[8]+=a.z*b.x; acc[9]+=a.z*b.y; acc[10]+=a.z*b.z; acc[11]+=a.z*b.w;
            acc[12]+=a.w*b.x; acc[13]+=a.w*b.y; acc[14]+=a.w*b.z; acc[15]+=a.w*b.w;
        }
        __syncthreads();
    }
    float4 bs = *(const float4*)(bf + tx * 4);
    float bcol[4] = {bs.x, bs.y, bs.z, bs.w};
    #pragma unroll
    for (int rr = 0; rr < 4; rr++) {
        int m = m0 + ty * 4 + rr;
        bool act = gap[m] > TAU;
        float4 o;
        float* op = (float*)&o;
        #pragma unroll
        for (int cc = 0; cc < 4; cc++) {
            float v = acc[rr * 4 + cc] + bcol[cc];
            op[cc] = act ? v : z[(size_t)m * 64 + tx * 4 + cc];
        }
        *(float4*)(out + (size_t)m * 64 + tx * 4) = o;
    }
}

// ---- sims + top-4: 128x128 tiles, 8 col-tiles per block, K=64 A-resident ----
// grid (32, 16), 512 threads (16 tx x 32 ty); thread: rows ty*4..+4, cols tx*8..+8
__global__ __launch_bounds__(512, 1) void sims_topk_kernel(
    const float* __restrict__ Q, const float* __restrict__ KN,
    float* __restrict__ pval, int* __restrict__ pidx)
{
    __shared__ float As[64 * 128];   // [k][m] 32KB
    __shared__ float Bs[16 * 128];   // [k][n] 8KB
    int tid = threadIdx.x;
    int tx = tid & 15, ty = tid >> 4;
    int m0 = blockIdx.x * 128;
    int cbase0 = blockIdx.y * 1024;

    // fill As (transposed, all K=64)
    {
        int row = tid & 127;
        int kq = tid >> 7;                  // 0..3 -> 16 ks each
        const float* src = Q + (size_t)(m0 + row) * 64 + kq * 16;
        #pragma unroll
        for (int j4 = 0; j4 < 4; j4++) {
            float4 v = *(const float4*)(src + j4 * 4);
            int kk = kq * 16 + j4 * 4;
            As[(kk + 0) * 128 + row] = v.x;
            As[(kk + 1) * 128 + row] = v.y;
            As[(kk + 2) * 128 + row] = v.z;
            As[(kk + 3) * 128 + row] = v.w;
        }
    }

    float tv[4][4];
    int   ti[4][4];
    #pragma unroll
    for (int r = 0; r < 4; r++)
        #pragma unroll
        for (int s = 0; s < 4; s++) { tv[r][s] = NEG; ti[r][s] = 0x7FFFFFFF; }

    for (int nt = 0; nt < 8; nt++) {
        int nbase = cbase0 + nt * 128;
        float acc[4][8];
        #pragma unroll
        for (int r = 0; r < 4; r++)
            #pragma unroll
            for (int c = 0; c < 8; c++) acc[r][c] = 0.f;

        #pragma unroll
        for (int kc = 0; kc < 4; kc++) {
            __syncthreads();
            {
                int row = tid & 127;
                int kq = tid >> 7;          // 0..3 -> 4 ks each
                float4 v = *(const float4*)(KN + (size_t)(nbase + row) * 64 + kc * 16 + kq * 4);
                Bs[(kq * 4 + 0) * 128 + row] = v.x;
                Bs[(kq * 4 + 1) * 128 + row] = v.y;
                Bs[(kq * 4 + 2) * 128 + row] = v.z;
                Bs[(kq * 4 + 3) * 128 + row] = v.w;
            }
            __syncthreads();
            #pragma unroll
            for (int k = 0; k < 16; k++) {
                int kk = kc * 16 + k;
                float4 a = *(const float4*)(As + kk * 128 + ty * 4);
                float4 b0 = *(const float4*)(Bs + k * 128 + tx * 8);
                float4 b1 = *(const float4*)(Bs + k * 128 + tx * 8 + 4);
                float av[4] = {a.x, a.y, a.z, a.w};
                float bv[8] = {b0.x, b0.y, b0.z, b0.w, b1.x, b1.y, b1.z, b1.w};
                #pragma unroll
                for (int r = 0; r < 4; r++)
                    #pragma unroll
                    for (int c = 0; c < 8; c++)
                        acc[r][c] += av[r] * bv[c];
            }
        }

        // top-4 insert (ids ascend within each row across nt/c)
        #pragma unroll
        for (int r = 0; r < 4; r++) {
            #pragma unroll
            for (int c = 0; c < 8; c++) {
                float v = acc[r][c];
                if (v > tv[r][3]) {
                    int id = nbase + tx * 8 + c;
                    ins4(tv[r], ti[r], v, id);
                }
            }
        }
    }

    // butterfly merge across the 16 tx lanes sharing each row (same warp)
    #pragma unroll
    for (int step = 1; step < 16; step <<= 1) {
        #pragma unroll
        for (int r = 0; r < 4; r++) {
            float ov[4]; int oi[4];
            #pragma unroll
            for (int s = 0; s < 4; s++) {
                ov[s] = __shfl_xor_sync(0xffffffffu, tv[r][s], step);
                oi[s] = __shfl_xor_sync(0xffffffffu, ti[r][s], step);
            }
            #pragma unroll
            for (int s = 0; s < 4; s++) ins4(tv[r], ti[r], ov[s], oi[s]);
        }
    }

    if (tx == 0) {
        #pragma unroll
        for (int r = 0; r < 4; r++) {
            int m = m0 + ty * 4 + r;
            int base = (m * 16 + blockIdx.y) * 4;
            #pragma unroll
            for (int s = 0; s < 4; s++) {
                pval[base + s] = tv[r][s];
                pidx[base + s] = ti[r][s];
            }
        }
    }
}

// merge per-split partials -> global top-4 -> v_ep -> v_combined
__global__ void ep_kernel(const float* __restrict__ pval, const int* __restrict__ pidx,
                          const float* __restrict__ cvals, const float* __restrict__ vmem,
                          float* __restrict__ vc)
{
    int b = blockIdx.x;
    __shared__ int sidx[4];
    if (threadIdx.x == 0) {
        float bv[4] = {NEG, NEG, NEG, NEG};
        int bi[4] = {0x7FFFFFFF, 0x7FFFFFFF, 0x7FFFFFFF, 0x7FFFFFFF};
        for (int j = 0; j < 64; j++) {
            float v = pval[b * 64 + j];
            int id = pidx[b * 64 + j];
            ins4(bv, bi, v, id);
        }
        sidx[0]=bi[0]; sidx[1]=bi[1]; sidx[2]=bi[2]; sidx[3]=bi[3];
    }
    __syncthreads();
    int e = threadIdx.x;
    float s = cvals[(size_t)sidx[0] * 64 + e];
    s += cvals[(size_t)sidx[1] * 64 + e];
    s += cvals[(size_t)sidx[2] * 64 + e];
    s += cvals[(size_t)sidx[3] * 64 + e];
    vc[b * 64 + e] = 0.5f * (vmem[b * 64 + e] + s * 0.25f);
}

__global__ void cf_partial_kernel(const float* __restrict__ z1, const float* __restrict__ z2,
                                  const float* __restrict__ z, const float* __restrict__ vc,
                                  float* __restrict__ part)
{
    __shared__ float red[256];
    float s = 0.f;
    for (int i = blockIdx.x * 256 + threadIdx.x; i < BB * DD; i += 256 * 256) {
        float d = 0.5f * (z1[i] + z2[i]) - z[i] - vc[i];
        s += d * d;
    }
    red[threadIdx.x] = s;
    __syncthreads();
    for (int st = 128; st > 0; st >>= 1) {
        if (threadIdx.x < st) red[threadIdx.x] += red[threadIdx.x + st];
        __syncthreads();
    }
    if (threadIdx.x == 0) part[blockIdx.x] = red[0];
}

__global__ void cf_final_kernel(const float* __restrict__ part, float* __restrict__ out)
{
    __shared__ float red[256];
    red[threadIdx.x] = part[threadIdx.x];
    __syncthreads();
    for (int st = 128; st > 0; st >>= 1) {
        if (threadIdx.x < st) red[threadIdx.x] += red[threadIdx.x + st];
        __syncthreads();
    }
    if (threadIdx.x == 0) out[BB * DD] = red[0] * (1.0f / (float)(BB * DD));
}

extern "C" void kernel_launch(void* const* d_in, const int* in_sizes, int n_in,
                              void* d_out, int out_size)
{
    const float* z    = (const float*)d_in[0];
    const float* hot  = (const float*)d_in[2];
    const float* gap  = (const float*)d_in[3];
    const float* Wq   = (const float*)d_in[4];
    const float* bq   = (const float*)d_in[5];
    const float* Wf   = (const float*)d_in[6];
    const float* bf   = (const float*)d_in[7];
    const float* mem  = (const float*)d_in[8];
    const float* Wk   = (const float*)d_in[9];
    const float* Wo   = (const float*)d_in[10];
    const float* ck   = (const float*)d_in[11];
    const float* cvals= (const float*)d_in[12];
    const float* aemb = (const float*)d_in[13];
    const float* Wih  = (const float*)d_in[14];
    const float* Whh  = (const float*)d_in[15];
    const float* bih  = (const float*)d_in[16];
    const float* bhh  = (const float*)d_in[17];
    const float* h0   = (const float*)d_in[18];
    const float* Wo1  = (const float*)d_in[19];
    const float* bo1  = (const float*)d_in[20];
    const float* Wo2  = (const float*)d_in[21];
    const float* bo2  = (const float*)d_in[22];
    const int*   acts = (const int*)d_in[23];
    float* out = (float*)d_out;

    float* scr = nullptr;
    cudaGetSymbolAddress((void**)&scr, d_scr);

    // tensor-product memory folded to 64x64 A
    prepA_kernel<<<8, 256>>>(mem, Wk, Wo, scr + OFF_APART);
    reduceAT_kernel<<<16, 256>>>(scr + OFF_APART, scr + OFF_AT);

    // query = (z*hot)@Wq^T + bq (premul fused); kn; v_mem = Q@A
    gemm_kernel<<<dim3(64, 1), 256>>>(z, hot, Wq, bq, scr + OFF_Q, 64, 64, 0);
    normalize_rows_kernel<<<2048, 256>>>(ck, scr + OFF_KN);
    gemm_kernel<<<dim3(64, 1), 256>>>(scr + OFF_Q, nullptr, scr + OFF_AT, scr + OFF_ZERO,
                                      scr + OFF_VMEM, 64, 64, 0);

    // episodic recall (Q unnormalized: per-row positive scaling preserves top-k)
    sims_topk_kernel<<<dim3(32, 16), 512>>>(scr + OFF_Q, scr + OFF_KN,
                                            scr + OFF_PVAL, (int*)(scr + OFF_PIDX));
    ep_kernel<<<BB, 64>>>(scr + OFF_PVAL, (int*)(scr + OFF_PIDX), cvals,
                          scr + OFF_VMEM, scr + OFF_VC);

    // GRU rollout, T=2; GH(t=0) collapses to a 384-vector (h0 rows identical)
    gh0_kernel<<<48, 256>>>(h0, Whh, bhh, scr + OFF_GH0);
    // t = 0
    buildx_kernel<<<2048, 256>>>(z, aemb, acts, 0, scr + OFF_X);
    gemm_kernel<<<dim3(64, 6), 256>>>(scr + OFF_X, nullptr, Wih, bih, scr + OFF_GI, 384, 128, 0);
    gates0_kernel<<<2048, 256>>>(scr + OFF_GI, scr + OFF_GH0, h0, scr + OFF_H2A);
    gemm_kernel<<<dim3(64, 2), 256>>>(scr + OFF_H2A, nullptr, Wo1, bo1, scr + OFF_HID, 128, 128, 1);
    gemm_kernel<<<dim3(64, 1), 256>>>(scr + OFF_HID, nullptr, Wo2, bo2, scr + OFF_Z1, 64, 128, 0);
    // t = 1
    buildx_kernel<<<2048, 256>>>(scr + OFF_Z1, aemb, acts, 1, scr + OFF_X);
    gemm_kernel<<<dim3(64, 6), 256>>>(scr + OFF_X, nullptr, Wih, bih, scr + OFF_GI, 384, 128, 0);
    gemm_kernel<<<dim3(64, 6), 256>>>(scr + OFF_H2A, nullptr, Whh, bhh, scr + OFF_GH, 384, 128, 0);
    gates_kernel<<<2048, 256>>>(scr + OFF_GI, scr + OFF_GH, scr + OFF_H2A, scr + OFF_H2B);
    gemm_kernel<<<dim3(64, 2), 256>>>(scr + OFF_H2B, nullptr, Wo1, bo1, scr + OFF_HID, 128, 128, 1);
    gemm_kernel<<<dim3(64, 1), 256>>>(scr + OFF_HID, nullptr, Wo2, bo2, scr + OFF_Z2, 64, 128, 0);

    // cf loss
    cf_partial_kernel<<<256, 256>>>(scr + OFF_Z1, scr + OFF_Z2, z, scr + OFF_VC, scr + OFF_CFP);
    cf_final_kernel<<<1, 256>>>(scr + OFF_CFP, out);

    // fused fusion + masked select
    fuse2_kernel<<<64, 256>>>(z, scr + OFF_VC, Wf, bf, gap, out);
}

// round 4
// speedup vs baseline: 1.3611x; 1.3611x over previous
#include <cuda_runtime.h>

#define BB 4096
#define DD 64
#define HH8 8
#define CC 16384
#define CSPLIT 8
#define CKEYS (CC / CSPLIT)     // 2048
#define TAU 0.3f
#define NEG (-1e30f)

// ---- scratch offsets (floats) ----
constexpr int OFF_AT    = 0;
constexpr int OFF_APART = OFF_AT    + 4096;
constexpr int OFF_KN    = OFF_APART + 32768;
constexpr int OFF_Q     = OFF_KN    + 1048576;
constexpr int OFF_VMEM  = OFF_Q     + 262144;
constexpr int OFF_VC    = OFF_VMEM  + 262144;
constexpr int OFF_PVAL  = OFF_VC    + 262144;   // 4096*8*4
constexpr int OFF_PIDX  = OFF_PVAL  + 131072;
constexpr int OFF_X     = OFF_PIDX  + 131072;
constexpr int OFF_GI    = OFF_X     + 524288;
constexpr int OFF_GH    = OFF_GI    + 1572864;
constexpr int OFF_H2A   = OFF_GH    + 1572864;
constexpr int OFF_H2B   = OFF_H2A   + 524288;
constexpr int OFF_HID   = OFF_H2B   + 524288;
constexpr int OFF_Z1    = OFF_HID   + 524288;
constexpr int OFF_Z2    = OFF_Z1    + 262144;
constexpr int OFF_GH0   = OFF_Z2    + 262144;   // 512
constexpr int OFF_CFP   = OFF_GH0   + 512;      // 256
constexpr int OFF_ZERO  = OFF_CFP   + 256;      // 512 zeros
constexpr int SCR_TOTAL = OFF_ZERO  + 512;

__device__ float d_scr[SCR_TOTAL];

#define BETTER(v,id,V,I) ((v) > (V) || ((v) == (V) && (id) < (I)))

__device__ __forceinline__ void ins4(float (&tv)[4], int (&ti)[4], float v, int id) {
    if (BETTER(v, id, tv[3], ti[3])) {
        if (BETTER(v, id, tv[0], ti[0])) {
            tv[3]=tv[2]; ti[3]=ti[2]; tv[2]=tv[1]; ti[2]=ti[1];
            tv[1]=tv[0]; ti[1]=ti[0]; tv[0]=v; ti[0]=id;
        } else if (BETTER(v, id, tv[1], ti[1])) {
            tv[3]=tv[2]; ti[3]=ti[2]; tv[2]=tv[1]; ti[2]=ti[1];
            tv[1]=v; ti[1]=id;
        } else if (BETTER(v, id, tv[2], ti[2])) {
            tv[3]=tv[2]; ti[3]=ti[2]; tv[2]=v; ti[2]=id;
        } else {
            tv[3]=v; ti[3]=id;
        }
    }
}

// packed fp32x2 FMA (Blackwell): d = a*b + d, two fp32 lanes per 64-bit reg
#define FMA2(d, a, b) asm("fma.rn.f32x2 %0, %1, %2, %0;" : "+l"(d) : "l"(a), "l"(b))
#define PACK2(o, lo, hi) asm("mov.b64 %0, {%1, %2};" : "=l"(o) : "r"(lo), "r"(hi))
#define UNPACK2(lo, hi, in) asm("mov.b64 {%0, %1}, %2;" : "=r"(lo), "=r"(hi) : "l"(in))

// ---- prep: Apart[h] = Wk_h^T @ (mem_h @ Wo^T) ----
__global__ void prepA_kernel(const float* __restrict__ mem,
                             const float* __restrict__ Wk,
                             const float* __restrict__ Wo,
                             float* __restrict__ Apart)
{
    int h = blockIdx.x;
    __shared__ float WoT[64 * 65];
    __shared__ float Mh[64 * 64];
    int t = threadIdx.x;
    #pragma unroll
    for (int p = 0; p < 16; p++) {
        int e = t + p * 256;
        int r = e >> 6, c = e & 63;
        WoT[c * 65 + r] = Wo[e];
    }
    __syncthreads();
    #pragma unroll
    for (int p = 0; p < 16; p++) {
        int e = t + p * 256;
        int dp = e >> 6, j = e & 63;
        const float* mrow = mem + h * 4096 + dp * 64;
        float s = 0.f;
        #pragma unroll
        for (int ee = 0; ee < 64; ee++) s += mrow[ee] * WoT[ee * 65 + j];
        Mh[dp * 64 + j] = s;
    }
    __syncthreads();
    #pragma unroll
    for (int p = 0; p < 16; p++) {
        int e = t + p * 256;
        int i = e >> 6, j = e & 63;
        float s = 0.f;
        #pragma unroll
        for (int dp = 0; dp < 64; dp++)
            s += Wk[(h * 64 + dp) * 64 + i] * Mh[dp * 64 + j];
        Apart[h * 4096 + e] = s;
    }
}

__global__ void reduceAT_kernel(const float* __restrict__ Apart,
                                float* __restrict__ AT)
{
    int e = blockIdx.x * 256 + threadIdx.x;
    int i = e >> 6, j = e & 63;
    float s = 0.f;
    #pragma unroll
    for (int h = 0; h < HH8; h++) s += Apart[h * 4096 + e];
    AT[j * 64 + i] = s * 0.125f;
}

// ---- row-normalize cache keys ----
__global__ void normalize_rows_kernel(const float* __restrict__ src,
                                      float* __restrict__ dst)
{
    int row  = blockIdx.x * 8 + (threadIdx.x >> 5);
    int lane = threadIdx.x & 31;
    float a = src[row * 64 + lane];
    float b = src[row * 64 + 32 + lane];
    float ss = a * a + b * b;
    #pragma unroll
    for (int off = 16; off > 0; off >>= 1)
        ss += __shfl_xor_sync(0xffffffffu, ss, off);
    float inv = 1.0f / fmaxf(sqrtf(ss), 1e-8f);
    dst[row * 64 + lane]      = a * inv;
    dst[row * 64 + 32 + lane] = b * inv;
}

// ---- gh0 = h0 @ Whh^T + bhh (384-vector) ----
__global__ void gh0_kernel(const float* __restrict__ h0, const float* __restrict__ Whh,
                           const float* __restrict__ bhh, float* __restrict__ gh0)
{
    int w = blockIdx.x * 8 + (threadIdx.x >> 5);
    int lane = threadIdx.x & 31;
    const float* row = Whh + w * 128;
    float s = row[lane] * h0[lane] + row[lane + 32] * h0[lane + 32]
            + row[lane + 64] * h0[lane + 64] + row[lane + 96] * h0[lane + 96];
    #pragma unroll
    for (int off = 16; off > 0; off >>= 1)
        s += __shfl_xor_sync(0xffffffffu, s, off);
    if (lane == 0) gh0[w] = s + bhh[w];
}

__global__ void buildx_kernel(const float* __restrict__ zprev,
                              const float* __restrict__ aemb,
                              const int* __restrict__ actions, int t,
                              float* __restrict__ x)
{
    int i = blockIdx.x * 256 + threadIdx.x;
    int b = i >> 7, p = i & 127;
    if (p < 64) x[i] = zprev[b * 64 + p];
    else        x[i] = aemb[actions[b * 2 + t] * 64 + (p - 64)];
}

__global__ void gates0_kernel(const float* __restrict__ gi, const float* __restrict__ gh0,
                              const float* __restrict__ h0, float* __restrict__ h2)
{
    int i = blockIdx.x * 256 + threadIdx.x;
    int b = i >> 7, j = i & 127;
    const float* gib = gi + b * 384;
    float r = 1.0f / (1.0f + expf(-(gib[j] + gh0[j])));
    float u = 1.0f / (1.0f + expf(-(gib[128 + j] + gh0[128 + j])));
    float n = tanhf(gib[256 + j] + r * gh0[256 + j]);
    float h = h0[j];
    h2[i] = (1.0f - u) * n + u * h;
}

__global__ void gates_kernel(const float* __restrict__ gi, const float* __restrict__ gh,
                             const float* __restrict__ hprev, float* __restrict__ h2)
{
    int i = blockIdx.x * 256 + threadIdx.x;
    int b = i >> 7, j = i & 127;
    const float* gib = gi + b * 384;
    const float* ghb = gh + b * 384;
    float r = 1.0f / (1.0f + expf(-(gib[j] + ghb[j])));
    float u = 1.0f / (1.0f + expf(-(gib[128 + j] + ghb[128 + j])));
    float n = tanhf(gib[256 + j] + r * ghb[256 + j]);
    float h = hprev[i];
    h2[i] = (1.0f - u) * n + u * h;
}

// ---- tiled GEMM: C = act((A?P) @ W^T + bias) ----
__global__ __launch_bounds__(256) void gemm_kernel(
    const float* __restrict__ A, const float* __restrict__ P,
    const float* __restrict__ W, const float* __restrict__ bias,
    float* __restrict__ Cm, int N, int K, int act)
{
    __shared__ float As[16 * 68];
    __shared__ float Ws[16 * 68];
    int tid = threadIdx.x;
    int tx = tid & 15, ty = tid >> 4;
    int m0 = blockIdx.x * 64, n0 = blockIdx.y * 64;
    float acc[16];
    #pragma unroll
    for (int q = 0; q < 16; q++) acc[q] = 0.f;
    int li = tid >> 2;
    int lj = (tid & 3) * 4;
    for (int kt = 0; kt < K; kt += 16) {
        float4 av = *(const float4*)(A + (size_t)(m0 + li) * K + kt + lj);
        if (P) {
            float4 pv = *(const float4*)(P + (size_t)(m0 + li) * K + kt + lj);
            av.x *= pv.x; av.y *= pv.y; av.z *= pv.z; av.w *= pv.w;
        }
        float4 wv = *(const float4*)(W + (size_t)(n0 + li) * K + kt + lj);
        As[(lj + 0) * 68 + li] = av.x; As[(lj + 1) * 68 + li] = av.y;
        As[(lj + 2) * 68 + li] = av.z; As[(lj + 3) * 68 + li] = av.w;
        Ws[(lj + 0) * 68 + li] = wv.x; Ws[(lj + 1) * 68 + li] = wv.y;
        Ws[(lj + 2) * 68 + li] = wv.z; Ws[(lj + 3) * 68 + li] = wv.w;
        __syncthreads();
        #pragma unroll
        for (int k = 0; k < 16; k++) {
            float4 a = *(const float4*)(As + k * 68 + ty * 4);
            float4 b = *(const float4*)(Ws + k * 68 + tx * 4);
            acc[0]+=a.x*b.x; acc[1]+=a.x*b.y; acc[2]+=a.x*b.z; acc[3]+=a.x*b.w;
            acc[4]+=a.y*b.x; acc[5]+=a.y*b.y; acc[6]+=a.y*b.z; acc[7]+=a.y*b.w;
            acc[8]+=a.z*b.x; acc[9]+=a.z*b.y; acc[10]+=a.z*b.z; acc[11]+=a.z*b.w;
            acc[12]+=a.w*b.x; acc[13]+=a.w*b.y; acc[14]+=a.w*b.z; acc[15]+=a.w*b.w;
        }
        __syncthreads();
    }
    float4 bs = *(const float4*)(bias + n0 + tx * 4);
    float bcol[4] = {bs.x, bs.y, bs.z, bs.w};
    #pragma unroll
    for (int rr = 0; rr < 4; rr++) {
        int m = m0 + ty * 4 + rr;
        float4 o;
        float* op = (float*)&o;
        #pragma unroll
        for (int cc = 0; cc < 4; cc++) {
            float v = acc[rr * 4 + cc] + bcol[cc];
            if (act == 1) v = 0.5f * v * (1.0f + erff(v * 0.70710678118654752f));
            op[cc] = v;
        }
        *(float4*)(Cm + (size_t)m * N + n0 + tx * 4) = o;
    }
}

// ---- fused fusion+select ----
__global__ __launch_bounds__(256) void fuse2_kernel(
    const float* __restrict__ z, const float* __restrict__ vc,
    const float* __restrict__ Wf, const float* __restrict__ bf,
    const float* __restrict__ gap, float* __restrict__ out)
{
    __shared__ float As[16 * 68];
    __shared__ float Ws[16 * 68];
    int tid = threadIdx.x;
    int tx = tid & 15, ty = tid >> 4;
    int m0 = blockIdx.x * 64;
    float acc[16];
    #pragma unroll
    for (int q = 0; q < 16; q++) acc[q] = 0.f;
    int li = tid >> 2;
    int lj = (tid & 3) * 4;
    for (int kt = 0; kt < 128; kt += 16) {
        const float* src = (kt < 64) ? (z + (size_t)(m0 + li) * 64 + kt + lj)
                                     : (vc + (size_t)(m0 + li) * 64 + (kt - 64) + lj);
        float4 av = *(const float4*)src;
        float4 wv = *(const float4*)(Wf + (size_t)li * 128 + kt + lj);
        As[(lj + 0) * 68 + li] = av.x; As[(lj + 1) * 68 + li] = av.y;
        As[(lj + 2) * 68 + li] = av.z; As[(lj + 3) * 68 + li] = av.w;
        Ws[(lj + 0) * 68 + li] = wv.x; Ws[(lj + 1) * 68 + li] = wv.y;
        Ws[(lj + 2) * 68 + li] = wv.z; Ws[(lj + 3) * 68 + li] = wv.w;
        __syncthreads();
        #pragma unroll
        for (int k = 0; k < 16; k++) {
            float4 a = *(const float4*)(As + k * 68 + ty * 4);
            float4 b = *(const float4*)(Ws + k * 68 + tx * 4);
            acc[0]+=a.x*b.x; acc[1]+=a.x*b.y; acc[2]+=a.x*b.z; acc[3]+=a.x*b.w;
            acc[4]+=a.y*b.x; acc[5]+=a.y*b.y; acc[6]+=a.y*b.z; acc[7]+=a.y*b.w;
            acc[8]+=a.z*b.x; acc[9]+=a.z*b.y; acc[10]+=a.z*b.z; acc[11]+=a.z*b.w;
            acc[12]+=a.w*b.x; acc[13]+=a.w*b.y; acc[14]+=a.w*b.z; acc[15]+=a.w*b.w;
        }
        __syncthreads();
    }
    float4 bs = *(const float4*)(bf + tx * 4);
    float bcol[4] = {bs.x, bs.y, bs.z, bs.w};
    #pragma unroll
    for (int rr = 0; rr < 4; rr++) {
        int m = m0 + ty * 4 + rr;
        bool act = gap[m] > TAU;
        float4 o;
        float* op = (float*)&o;
        #pragma unroll
        for (int cc = 0; cc < 4; cc++) {
            float v = acc[rr * 4 + cc] + bcol[cc];
            op[cc] = act ? v : z[(size_t)m * 64 + tx * 4 + cc];
        }
        *(float4*)(out + (size_t)m * 64 + tx * 4) = o;
    }
}

// ---- sims + top-4, packed f32x2 math ----
// grid (64 m-tiles, CSPLIT), 256 threads (16tx x 16ty).
// Block: 64 q-rows resident (q_s [k][m], stride 64), loops 16 chunks of 128 keys.
// Thread: rows ty*4..+3, cols {tx*4..+3} u {64+tx*4..+3} -> 4x8 via 16 f32x2 accs.
__global__ __launch_bounds__(256) void sims_topk_kernel(
    const float* __restrict__ Q, const float* __restrict__ KN,
    float* __restrict__ pval, int* __restrict__ pidx)
{
    __shared__ float q_s[64 * 64];    // 16 KB  [k][m]
    __shared__ float k_s[64 * 128];   // 32 KB  [k][n]
    int tid = threadIdx.x;
    int tx = tid & 15, ty = tid >> 4;
    int m0 = blockIdx.x * 64;
    int c0 = blockIdx.y * CKEYS;

    // fill q_s transposed: thread row = tid&63, k-quarter = tid>>6
    {
        int row = tid & 63;
        int kq = tid >> 6;                 // 0..3 -> 16 ks each
        const float* src = Q + (size_t)(m0 + row) * 64 + kq * 16;
        #pragma unroll
        for (int j4 = 0; j4 < 4; j4++) {
            float4 v = *(const float4*)(src + j4 * 4);
            int kk = kq * 16 + j4 * 4;
            q_s[(kk + 0) * 64 + row] = v.x;
            q_s[(kk + 1) * 64 + row] = v.y;
            q_s[(kk + 2) * 64 + row] = v.z;
            q_s[(kk + 3) * 64 + row] = v.w;
        }
    }

    float tv[4][4];
    int   ti[4][4];
    #pragma unroll
    for (int r = 0; r < 4; r++)
        #pragma unroll
        for (int s = 0; s < 4; s++) { tv[r][s] = NEG; ti[r][s] = 0x7FFFFFFF; }

    for (int nt = 0; nt < CKEYS / 128; nt++) {
        int nbase = c0 + nt * 128;
        __syncthreads();
        // fill k_s transposed: thread n = tid&127, k-half = tid>>7 (32 ks)
        {
            int n = tid & 127;
            int kh = tid >> 7;             // 0..1
            const float* src = KN + (size_t)(nbase + n) * 64 + kh * 32;
            #pragma unroll
            for (int j4 = 0; j4 < 8; j4++) {
                float4 v = *(const float4*)(src + j4 * 4);
                int kk = kh * 32 + j4 * 4;
                k_s[(kk + 0) * 128 + n] = v.x;
                k_s[(kk + 1) * 128 + n] = v.y;
                k_s[(kk + 2) * 128 + n] = v.z;
                k_s[(kk + 3) * 128 + n] = v.w;
            }
        }
        __syncthreads();

        unsigned long long acc[4][4];
        #pragma unroll
        for (int r = 0; r < 4; r++)
            #pragma unroll
            for (int c = 0; c < 4; c++) acc[r][c] = 0ull;

        #pragma unroll 4
        for (int k = 0; k < 64; k++) {
            float4 a = *(const float4*)(q_s + k * 64 + ty * 4);
            ulonglong2 bA = *(const ulonglong2*)(k_s + k * 128 + tx * 4);
            ulonglong2 bB = *(const ulonglong2*)(k_s + k * 128 + 64 + tx * 4);
            unsigned long long ap[4];
            PACK2(ap[0], __float_as_uint(a.x), __float_as_uint(a.x));
            PACK2(ap[1], __float_as_uint(a.y), __float_as_uint(a.y));
            PACK2(ap[2], __float_as_uint(a.z), __float_as_uint(a.z));
            PACK2(ap[3], __float_as_uint(a.w), __float_as_uint(a.w));
            #pragma unroll
            for (int r = 0; r < 4; r++) {
                FMA2(acc[r][0], ap[r], bA.x);
                FMA2(acc[r][1], ap[r], bA.y);
                FMA2(acc[r][2], ap[r], bB.x);
                FMA2(acc[r][3], ap[r], bB.y);
            }
        }

        // unpack + top-4 insert; ids ascend: group A (tx*4..+3) then B (64+tx*4..+3)
        #pragma unroll
        for (int r = 0; r < 4; r++) {
            #pragma unroll
            for (int c = 0; c < 4; c++) {
                unsigned int lo, hi;
                UNPACK2(lo, hi, acc[r][c]);
                float vlo = __uint_as_float(lo);
                float vhi = __uint_as_float(hi);
                int idbase = nbase + ((c < 2) ? (tx * 4 + c * 2) : (64 + tx * 4 + (c - 2) * 2));
                if (vlo > tv[r][3]) ins4(tv[r], ti[r], vlo, idbase);
                if (vhi > tv[r][3]) ins4(tv[r], ti[r], vhi, idbase + 1);
            }
        }
    }

    // butterfly merge across 16 tx lanes sharing each row
    #pragma unroll
    for (int step = 1; step < 16; step <<= 1) {
        #pragma unroll
        for (int r = 0; r < 4; r++) {
            float ov[4]; int oi[4];
            #pragma unroll
            for (int s = 0; s < 4; s++) {
                ov[s] = __shfl_xor_sync(0xffffffffu, tv[r][s], step);
                oi[s] = __shfl_xor_sync(0xffffffffu, ti[r][s], step);
            }
            #pragma unroll
            for (int s = 0; s < 4; s++) ins4(tv[r], ti[r], ov[s], oi[s]);
        }
    }

    if (tx == 0) {
        #pragma unroll
        for (int r = 0; r < 4; r++) {
            int m = m0 + ty * 4 + r;
            int base = (m * CSPLIT + blockIdx.y) * 4;
            #pragma unroll
            for (int s = 0; s < 4; s++) {
                pval[base + s] = tv[r][s];
                pidx[base + s] = ti[r][s];
            }
        }
    }
}

// merge per-split partials -> global top-4 -> v_ep -> v_combined
__global__ void ep_kernel(const float* __restrict__ pval, const int* __restrict__ pidx,
                          const float* __restrict__ cvals, const float* __restrict__ vmem,
                          float* __restrict__ vc)
{
    int b = blockIdx.x;
    __shared__ int sidx[4];
    if (threadIdx.x == 0) {
        float bv[4] = {NEG, NEG, NEG, NEG};
        int bi[4] = {0x7FFFFFFF, 0x7FFFFFFF, 0x7FFFFFFF, 0x7FFFFFFF};
        for (int j = 0; j < CSPLIT * 4; j++) {
            float v = pval[b * (CSPLIT * 4) + j];
            int id = pidx[b * (CSPLIT * 4) + j];
            ins4(bv, bi, v, id);
        }
        sidx[0]=bi[0]; sidx[1]=bi[1]; sidx[2]=bi[2]; sidx[3]=bi[3];
    }
    __syncthreads();
    int e = threadIdx.x;
    float s = cvals[(size_t)sidx[0] * 64 + e];
    s += cvals[(size_t)sidx[1] * 64 + e];
    s += cvals[(size_t)sidx[2] * 64 + e];
    s += cvals[(size_t)sidx[3] * 64 + e];
    vc[b * 64 + e] = 0.5f * (vmem[b * 64 + e] + s * 0.25f);
}

__global__ void cf_partial_kernel(const float* __restrict__ z1, const float* __restrict__ z2,
                                  const float* __restrict__ z, const float* __restrict__ vc,
                                  float* __restrict__ part)
{
    __shared__ float red[256];
    float s = 0.f;
    for (int i = blockIdx.x * 256 + threadIdx.x; i < BB * DD; i += 256 * 256) {
        float d = 0.5f * (z1[i] + z2[i]) - z[i] - vc[i];
        s += d * d;
    }
    red[threadIdx.x] = s;
    __syncthreads();
    for (int st = 128; st > 0; st >>= 1) {
        if (threadIdx.x < st) red[threadIdx.x] += red[threadIdx.x + st];
        __syncthreads();
    }
    if (threadIdx.x == 0) part[blockIdx.x] = red[0];
}

__global__ void cf_final_kernel(const float* __restrict__ part, float* __restrict__ out)
{
    __shared__ float red[256];
    red[threadIdx.x] = part[threadIdx.x];
    __syncthreads();
    for (int st = 128; st > 0; st >>= 1) {
        if (threadIdx.x < st) red[threadIdx.x] += red[threadIdx.x + st];
        __syncthreads();
    }
    if (threadIdx.x == 0) out[BB * DD] = red[0] * (1.0f / (float)(BB * DD));
}

extern "C" void kernel_launch(void* const* d_in, const int* in_sizes, int n_in,
                              void* d_out, int out_size)
{
    const float* z    = (const float*)d_in[0];
    const float* hot  = (const float*)d_in[2];
    const float* gap  = (const float*)d_in[3];
    const float* Wq   = (const float*)d_in[4];
    const float* bq   = (const float*)d_in[5];
    const float* Wf   = (const float*)d_in[6];
    const float* bf   = (const float*)d_in[7];
    const float* mem  = (const float*)d_in[8];
    const float* Wk   = (const float*)d_in[9];
    const float* Wo   = (const float*)d_in[10];
    const float* ck   = (const float*)d_in[11];
    const float* cvals= (const float*)d_in[12];
    const float* aemb = (const float*)d_in[13];
    const float* Wih  = (const float*)d_in[14];
    const float* Whh  = (const float*)d_in[15];
    const float* bih  = (const float*)d_in[16];
    const float* bhh  = (const float*)d_in[17];
    const float* h0   = (const float*)d_in[18];
    const float* Wo1  = (const float*)d_in[19];
    const float* bo1  = (const float*)d_in[20];
    const float* Wo2  = (const float*)d_in[21];
    const float* bo2  = (const float*)d_in[22];
    const int*   acts = (const int*)d_in[23];
    float* out = (float*)d_out;

    float* scr = nullptr;
    cudaGetSymbolAddress((void**)&scr, d_scr);

    // tensor-product memory folded to 64x64 A
    prepA_kernel<<<8, 256>>>(mem, Wk, Wo, scr + OFF_APART);
    reduceAT_kernel<<<16, 256>>>(scr + OFF_APART, scr + OFF_AT);

    // query = (z*hot)@Wq^T + bq (premul fused); kn; v_mem = Q@A
    gemm_kernel<<<dim3(64, 1), 256>>>(z, hot, Wq, bq, scr + OFF_Q, 64, 64, 0);
    normalize_rows_kernel<<<2048, 256>>>(ck, scr + OFF_KN);
    gemm_kernel<<<dim3(64, 1), 256>>>(scr + OFF_Q, nullptr, scr + OFF_AT, scr + OFF_ZERO,
                                      scr + OFF_VMEM, 64, 64, 0);

    // episodic recall (Q unnormalized: positive per-row scaling preserves top-k)
    sims_topk_kernel<<<dim3(64, CSPLIT), 256>>>(scr + OFF_Q, scr + OFF_KN,
                                                scr + OFF_PVAL, (int*)(scr + OFF_PIDX));
    ep_kernel<<<BB, 64>>>(scr + OFF_PVAL, (int*)(scr + OFF_PIDX), cvals,
                          scr + OFF_VMEM, scr + OFF_VC);

    // GRU rollout, T=2; GH(t=0) collapses to a 384-vector
    gh0_kernel<<<48, 256>>>(h0, Whh, bhh, scr + OFF_GH0);
    // t = 0
    buildx_kernel<<<2048, 256>>>(z, aemb, acts, 0, scr + OFF_X);
    gemm_kernel<<<dim3(64, 6), 256>>>(scr + OFF_X, nullptr, Wih, bih, scr + OFF_GI, 384, 128, 0);
    gates0_kernel<<<2048, 256>>>(scr + OFF_GI, scr + OFF_GH0, h0, scr + OFF_H2A);
    gemm_kernel<<<dim3(64, 2), 256>>>(scr + OFF_H2A, nullptr, Wo1, bo1, scr + OFF_HID, 128, 128, 1);
    gemm_kernel<<<dim3(64, 1), 256>>>(scr + OFF_HID, nullptr, Wo2, bo2, scr + OFF_Z1, 64, 128, 0);
    // t = 1
    buildx_kernel<<<2048, 256>>>(scr + OFF_Z1, aemb, acts, 1, scr + OFF_X);
    gemm_kernel<<<dim3(64, 6), 256>>>(scr + OFF_X, nullptr, Wih, bih, scr + OFF_GI, 384, 128, 0);
    gemm_kernel<<<dim3(64, 6), 256>>>(scr + OFF_H2A, nullptr, Whh, bhh, scr + OFF_GH, 384, 128, 0);
    gates_kernel<<<2048, 256>>>(scr + OFF_GI, scr + OFF_GH, scr + OFF_H2A, scr + OFF_H2B);
    gemm_kernel<<<dim3(64, 2), 256>>>(scr + OFF_H2B, nullptr, Wo1, bo1, scr + OFF_HID, 128, 128, 1);
    gemm_kernel<<<dim3(64, 1), 256>>>(scr + OFF_HID, nullptr, Wo2, bo2, scr + OFF_Z2, 64, 128, 0);

    // cf loss
    cf_partial_kernel<<<256, 256>>>(scr + OFF_Z1, scr + OFF_Z2, z, scr + OFF_VC, scr + OFF_CFP);
    cf_final_kernel<<<1, 256>>>(scr + OFF_CFP, out);

    // fused fusion + masked select
    fuse2_kernel<<<64, 256>>>(z, scr + OFF_VC, Wf, bf, gap, out);
}

// round 7
// speedup vs baseline: 1.9003x; 1.3962x over previous
#include <cuda_runtime.h>
#include <cuda_bf16.h>
#include <cstdint>

#define BB 4096
#define DD 64
#define HH8 8
#define CC 16384
#define TAU 0.3f
#define NEG (-1e30f)

// ---- scratch offsets (floats) ----
constexpr int OFF_AT    = 0;
constexpr int OFF_APART = OFF_AT    + 4096;
constexpr int OFF_KN    = OFF_APART + 32768;
constexpr int OFF_Q     = OFF_KN    + 1048576;
constexpr int OFF_VMEM  = OFF_Q     + 262144;
constexpr int OFF_VC    = OFF_VMEM  + 262144;
constexpr int OFF_PIDX  = OFF_VC    + 262144;   // 4096*8*16 ints = 524288
constexpr int OFF_QH    = OFF_PIDX  + 524288;   // 4096*64 bf16
constexpr int OFF_KNH   = OFF_QH    + 131072;   // 16384*64 bf16
constexpr int OFF_X     = OFF_KNH   + 524288;
constexpr int OFF_GI    = OFF_X     + 524288;
constexpr int OFF_GH    = OFF_GI    + 1572864;
constexpr int OFF_H2A   = OFF_GH    + 1572864;
constexpr int OFF_H2B   = OFF_H2A   + 524288;
constexpr int OFF_HID   = OFF_H2B   + 524288;
constexpr int OFF_Z1    = OFF_HID   + 524288;
constexpr int OFF_Z2    = OFF_Z1    + 262144;
constexpr int OFF_GH0   = OFF_Z2    + 262144;   // 512
constexpr int OFF_CFP   = OFF_GH0   + 512;      // 256
constexpr int OFF_ZERO  = OFF_CFP   + 256;      // 512 zeros
constexpr int SCR_TOTAL = OFF_ZERO  + 512;

__device__ float d_scr[SCR_TOTAL];

#define BETTER(v,id,V,I) ((v) > (V) || ((v) == (V) && (id) < (I)))

__device__ __forceinline__ void ins4(float (&tv)[4], int (&ti)[4], float v, int id) {
    if (BETTER(v, id, tv[3], ti[3])) {
        if (BETTER(v, id, tv[0], ti[0])) {
            tv[3]=tv[2]; ti[3]=ti[2]; tv[2]=tv[1]; ti[2]=ti[1];
            tv[1]=tv[0]; ti[1]=ti[0]; tv[0]=v; ti[0]=id;
        } else if (BETTER(v, id, tv[1], ti[1])) {
            tv[3]=tv[2]; ti[3]=ti[2]; tv[2]=tv[1]; ti[2]=ti[1];
            tv[1]=v; ti[1]=id;
        } else if (BETTER(v, id, tv[2], ti[2])) {
            tv[3]=tv[2]; ti[3]=ti[2]; tv[2]=v; ti[2]=id;
        } else {
            tv[3]=v; ti[3]=id;
        }
    }
}

// top-8 insertion (candidate-set membership; exact order fixed by fp32 rescore)
__device__ __forceinline__ void ins8(float (&tv)[8], int (&ti)[8], float v, int id) {
    if (!(v > tv[7])) return;
    #pragma unroll
    for (int s = 7; s >= 1; s--) {
        if (v > tv[s-1])      { tv[s] = tv[s-1]; ti[s] = ti[s-1]; }
        else if (v > tv[s])   { tv[s] = v;       ti[s] = id;      }
    }
    if (v > tv[0]) { tv[0] = v; ti[0] = id; }
}

__device__ __forceinline__ uint32_t smem_u32(const void* p) {
    uint32_t a;
    asm("{ .reg .u64 t; cvta.to.shared.u64 t, %1; cvt.u32.u64 %0, t; }" : "=r"(a) : "l"(p));
    return a;
}
#define SW128(o) ((o) ^ (((o) >> 3) & 0x70))

// ======================= prep kernels =======================
__global__ void prepA_kernel(const float* __restrict__ mem,
                             const float* __restrict__ Wk,
                             const float* __restrict__ Wo,
                             float* __restrict__ Apart)
{
    int h = blockIdx.x;
    __shared__ float WoT[64 * 65];
    __shared__ float Mh[64 * 64];
    int t = threadIdx.x;
    #pragma unroll
    for (int p = 0; p < 16; p++) {
        int e = t + p * 256;
        int r = e >> 6, c = e & 63;
        WoT[c * 65 + r] = Wo[e];
    }
    __syncthreads();
    #pragma unroll
    for (int p = 0; p < 16; p++) {
        int e = t + p * 256;
        int dp = e >> 6, j = e & 63;
        const float* mrow = mem + h * 4096 + dp * 64;
        float s = 0.f;
        #pragma unroll
        for (int ee = 0; ee < 64; ee++) s += mrow[ee] * WoT[ee * 65 + j];
        Mh[dp * 64 + j] = s;
    }
    __syncthreads();
    #pragma unroll
    for (int p = 0; p < 16; p++) {
        int e = t + p * 256;
        int i = e >> 6, j = e & 63;
        float s = 0.f;
        #pragma unroll
        for (int dp = 0; dp < 64; dp++)
            s += Wk[(h * 64 + dp) * 64 + i] * Mh[dp * 64 + j];
        Apart[h * 4096 + e] = s;
    }
}

__global__ void reduceAT_kernel(const float* __restrict__ Apart,
                                float* __restrict__ AT)
{
    int e = blockIdx.x * 256 + threadIdx.x;
    int i = e >> 6, j = e & 63;
    float s = 0.f;
    #pragma unroll
    for (int h = 0; h < HH8; h++) s += Apart[h * 4096 + e];
    AT[j * 64 + i] = s * 0.125f;
}

// normalize cache keys; emit fp32 (rescore) + bf16 (tensor-core) copies
__global__ void normalize_rows_kernel(const float* __restrict__ src,
                                      float* __restrict__ dst,
                                      __nv_bfloat16* __restrict__ dsth)
{
    int row  = blockIdx.x * 8 + (threadIdx.x >> 5);
    int lane = threadIdx.x & 31;
    float a = src[row * 64 + lane];
    float b = src[row * 64 + 32 + lane];
    float ss = a * a + b * b;
    #pragma unroll
    for (int off = 16; off > 0; off >>= 1)
        ss += __shfl_xor_sync(0xffffffffu, ss, off);
    float inv = 1.0f / fmaxf(sqrtf(ss), 1e-8f);
    float na = a * inv, nb = b * inv;
    dst[row * 64 + lane]       = na;
    dst[row * 64 + 32 + lane]  = nb;
    dsth[row * 64 + lane]      = __float2bfloat16(na);
    dsth[row * 64 + 32 + lane] = __float2bfloat16(nb);
}

__global__ void gh0_kernel(const float* __restrict__ h0, const float* __restrict__ Whh,
                           const float* __restrict__ bhh, float* __restrict__ gh0)
{
    int w = blockIdx.x * 8 + (threadIdx.x >> 5);
    int lane = threadIdx.x & 31;
    const float* row = Whh + w * 128;
    float s = row[lane] * h0[lane] + row[lane + 32] * h0[lane + 32]
            + row[lane + 64] * h0[lane + 64] + row[lane + 96] * h0[lane + 96];
    #pragma unroll
    for (int off = 16; off > 0; off >>= 1)
        s += __shfl_xor_sync(0xffffffffu, s, off);
    if (lane == 0) gh0[w] = s + bhh[w];
}

__global__ void buildx_kernel(const float* __restrict__ zprev,
                              const float* __restrict__ aemb,
                              const int* __restrict__ actions, int t,
                              float* __restrict__ x)
{
    int i = blockIdx.x * 256 + threadIdx.x;
    int b = i >> 7, p = i & 127;
    if (p < 64) x[i] = zprev[b * 64 + p];
    else        x[i] = aemb[actions[b * 2 + t] * 64 + (p - 64)];
}

__global__ void gates0_kernel(const float* __restrict__ gi, const float* __restrict__ gh0,
                              const float* __restrict__ h0, float* __restrict__ h2)
{
    int i = blockIdx.x * 256 + threadIdx.x;
    int b = i >> 7, j = i & 127;
    const float* gib = gi + b * 384;
    float r = 1.0f / (1.0f + expf(-(gib[j] + gh0[j])));
    float u = 1.0f / (1.0f + expf(-(gib[128 + j] + gh0[128 + j])));
    float n = tanhf(gib[256 + j] + r * gh0[256 + j]);
    float h = h0[j];
    h2[i] = (1.0f - u) * n + u * h;
}

__global__ void gates_kernel(const float* __restrict__ gi, const float* __restrict__ gh,
                             const float* __restrict__ hprev, float* __restrict__ h2)
{
    int i = blockIdx.x * 256 + threadIdx.x;
    int b = i >> 7, j = i & 127;
    const float* gib = gi + b * 384;
    const float* ghb = gh + b * 384;
    float r = 1.0f / (1.0f + expf(-(gib[j] + ghb[j])));
    float u = 1.0f / (1.0f + expf(-(gib[128 + j] + ghb[128 + j])));
    float n = tanhf(gib[256 + j] + r * ghb[256 + j]);
    float h = hprev[i];
    h2[i] = (1.0f - u) * n + u * h;
}

// ---- tiled GEMM: C = act((A?P) @ W^T + bias); optional bf16 mirror ----
__global__ __launch_bounds__(256) void gemm_kernel(
    const float* __restrict__ A, const float* __restrict__ P,
    const float* __restrict__ W, const float* __restrict__ bias,
    float* __restrict__ Cm, int N, int K, int act,
    __nv_bfloat16* __restrict__ Ch)
{
    __shared__ float As[16 * 68];
    __shared__ float Ws[16 * 68];
    int tid = threadIdx.x;
    int tx = tid & 15, ty = tid >> 4;
    int m0 = blockIdx.x * 64, n0 = blockIdx.y * 64;
    float acc[16];
    #pragma unroll
    for (int q = 0; q < 16; q++) acc[q] = 0.f;
    int li = tid >> 2;
    int lj = (tid & 3) * 4;
    for (int kt = 0; kt < K; kt += 16) {
        float4 av = *(const float4*)(A + (size_t)(m0 + li) * K + kt + lj);
        if (P) {
            float4 pv = *(const float4*)(P + (size_t)(m0 + li) * K + kt + lj);
            av.x *= pv.x; av.y *= pv.y; av.z *= pv.z; av.w *= pv.w;
        }
        float4 wv = *(const float4*)(W + (size_t)(n0 + li) * K + kt + lj);
        As[(lj + 0) * 68 + li] = av.x; As[(lj + 1) * 68 + li] = av.y;
        As[(lj + 2) * 68 + li] = av.z; As[(lj + 3) * 68 + li] = av.w;
        Ws[(lj + 0) * 68 + li] = wv.x; Ws[(lj + 1) * 68 + li] = wv.y;
        Ws[(lj + 2) * 68 + li] = wv.z; Ws[(lj + 3) * 68 + li] = wv.w;
        __syncthreads();
        #pragma unroll
        for (int k = 0; k < 16; k++) {
            float4 a = *(const float4*)(As + k * 68 + ty * 4);
            float4 b = *(const float4*)(Ws + k * 68 + tx * 4);
            acc[0]+=a.x*b.x; acc[1]+=a.x*b.y; acc[2]+=a.x*b.z; acc[3]+=a.x*b.w;
            acc[4]+=a.y*b.x; acc[5]+=a.y*b.y; acc[6]+=a.y*b.z; acc[7]+=a.y*b.w;
            acc[8]+=a.z*b.x; acc[9]+=a.z*b.y; acc[10]+=a.z*b.z; acc[11]+=a.z*b.w;
            acc[12]+=a.w*b.x; acc[13]+=a.w*b.y; acc[14]+=a.w*b.z; acc[15]+=a.w*b.w;
        }
        __syncthreads();
    }
    float4 bs = *(const float4*)(bias + n0 + tx * 4);
    float bcol[4] = {bs.x, bs.y, bs.z, bs.w};
    #pragma unroll
    for (int rr = 0; rr < 4; rr++) {
        int m = m0 + ty * 4 + rr;
        float4 o;
        float* op = (float*)&o;
        #pragma unroll
        for (int cc = 0; cc < 4; cc++) {
            float v = acc[rr * 4 + cc] + bcol[cc];
            if (act == 1) v = 0.5f * v * (1.0f + erff(v * 0.70710678118654752f));
            op[cc] = v;
        }
        *(float4*)(Cm + (size_t)m * N + n0 + tx * 4) = o;
        if (Ch) {
            #pragma unroll
            for (int cc = 0; cc < 4; cc++)
                Ch[(size_t)m * N + n0 + tx * 4 + cc] = __float2bfloat16(op[cc]);
        }
    }
}

// ---- fused fusion+select ----
__global__ __launch_bounds__(256) void fuse2_kernel(
    const float* __restrict__ z, const float* __restrict__ vc,
    const float* __restrict__ Wf, const float* __restrict__ bf,
    const float* __restrict__ gap, float* __restrict__ out)
{
    __shared__ float As[16 * 68];
    __shared__ float Ws[16 * 68];
    int tid = threadIdx.x;
    int tx = tid & 15, ty = tid >> 4;
    int m0 = blockIdx.x * 64;
    float acc[16];
    #pragma unroll
    for (int q = 0; q < 16; q++) acc[q] = 0.f;
    int li = tid >> 2;
    int lj = (tid & 3) * 4;
    for (int kt = 0; kt < 128; kt += 16) {
        const float* src = (kt < 64) ? (z + (size_t)(m0 + li) * 64 + kt + lj)
                                     : (vc + (size_t)(m0 + li) * 64 + (kt - 64) + lj);
        float4 av = *(const float4*)src;
        float4 wv = *(const float4*)(Wf + (size_t)li * 128 + kt + lj);
        As[(lj + 0) * 68 + li] = av.x; As[(lj + 1) * 68 + li] = av.y;
        As[(lj + 2) * 68 + li] = av.z; As[(lj + 3) * 68 + li] = av.w;
        Ws[(lj + 0) * 68 + li] = wv.x; Ws[(lj + 1) * 68 + li] = wv.y;
        Ws[(lj + 2) * 68 + li] = wv.z; Ws[(lj + 3) * 68 + li] = wv.w;
        __syncthreads();
        #pragma unroll
        for (int k = 0; k < 16; k++) {
            float4 a = *(const float4*)(As + k * 68 + ty * 4);
            float4 b = *(const float4*)(Ws + k * 68 + tx * 4);
            acc[0]+=a.x*b.x; acc[1]+=a.x*b.y; acc[2]+=a.x*b.z; acc[3]+=a.x*b.w;
            acc[4]+=a.y*b.x; acc[5]+=a.y*b.y; acc[6]+=a.y*b.z; acc[7]+=a.y*b.w;
            acc[8]+=a.z*b.x; acc[9]+=a.z*b.y; acc[10]+=a.z*b.z; acc[11]+=a.z*b.w;
            acc[12]+=a.w*b.x; acc[13]+=a.w*b.y; acc[14]+=a.w*b.z; acc[15]+=a.w*b.w;
        }
        __syncthreads();
    }
    float4 bs = *(const float4*)(bf + tx * 4);
    float bcol[4] = {bs.x, bs.y, bs.z, bs.w};
    #pragma unroll
    for (int rr = 0; rr < 4; rr++) {
        int m = m0 + ty * 4 + rr;
        bool act = gap[m] > TAU;
        float4 o;
        float* op = (float*)&o;
        #pragma unroll
        for (int cc = 0; cc < 4; cc++) {
            float v = acc[rr * 4 + cc] + bcol[cc];
            op[cc] = act ? v : z[(size_t)m * 64 + tx * 4 + cc];
        }
        *(float4*)(out + (size_t)m * 64 + tx * 4) = o;
    }
}

// =============== HMMA sims screen: bf16 mma.sync + per-row top-8 ===============
// grid (64 m-tiles, 8 splits), 256 threads = 8 warps.
// Warp w: rows msub=(w&3)*16, key-half nhalf=w>>2. Each (row, split, half) gets
// its OWN pidx slot (16 candidates per row-split; no cross-warp races).
__global__ __launch_bounds__(256) void mma_sims_kernel(
    const __nv_bfloat16* __restrict__ Qh,
    const __nv_bfloat16* __restrict__ KNh,
    int* __restrict__ pidx)
{
    __shared__ __align__(1024) char sm[8192 + 16384];
    const uint32_t QOFF = 0, KOFF = 8192;
    uint32_t smb = smem_u32(sm);
    int tid = threadIdx.x;
    int warp = tid >> 5, lane = tid & 31;
    int msub = (warp & 3) * 16;
    int nhalf = warp >> 2;
    int m0 = blockIdx.x * 64;
    int c0 = blockIdx.y * 2048;

    // Q tile: 64 rows x 64 bf16 (128B rows, SW128)
    #pragma unroll
    for (int p = 0; p < 2; p++) {
        int c = tid + p * 256;              // 512 chunks of 16B
        int row = c >> 3, kc = c & 7;
        uint4 v = *(const uint4*)(Qh + (size_t)(m0 + row) * 64 + kc * 8);
        *(uint4*)(sm + QOFF + SW128((uint32_t)(row * 128 + kc * 16))) = v;
    }

    float tv[2][8]; int ti[2][8];
    #pragma unroll
    for (int r = 0; r < 2; r++)
        #pragma unroll
        for (int s = 0; s < 8; s++) { tv[r][s] = NEG; ti[r][s] = 0x7FFFFFFF; }

    for (int it = 0; it < 16; it++) {
        int nbase = c0 + it * 128;
        __syncthreads();
        // K tile: 128 key-rows x 64 bf16 (SW128)
        #pragma unroll
        for (int p = 0; p < 4; p++) {
            int c = tid + p * 256;          // 1024 chunks
            int row = c >> 3, kc = c & 7;
            uint4 v = *(const uint4*)(KNh + (size_t)(nbase + row) * 64 + kc * 8);
            *(uint4*)(sm + KOFF + SW128((uint32_t)(row * 128 + kc * 16))) = v;
        }
        __syncthreads();

        float acc[8][4];
        #pragma unroll
        for (int j = 0; j < 8; j++)
            #pragma unroll
            for (int q = 0; q < 4; q++) acc[j][q] = 0.f;

        #pragma unroll
        for (int kk = 0; kk < 4; kk++) {
            uint32_t a0, a1, a2, a3;
            uint32_t aaddr = smb + QOFF +
                SW128((uint32_t)((msub + (lane & 15)) * 128 + kk * 32 + (lane >> 4) * 16));
            asm volatile("ldmatrix.sync.aligned.m8n8.x4.shared.b16 {%0,%1,%2,%3}, [%4];"
                         : "=r"(a0), "=r"(a1), "=r"(a2), "=r"(a3) : "r"(aaddr));
            #pragma unroll
            for (int j = 0; j < 8; j++) {
                int keyrow = nhalf * 64 + j * 8 + (lane & 7);
                uint32_t baddr = smb + KOFF +
                    SW128((uint32_t)(keyrow * 128 + kk * 32 + ((lane >> 3) & 1) * 16));
                uint32_t b0, b1;
                asm volatile("ldmatrix.sync.aligned.m8n8.x2.shared.b16 {%0,%1}, [%2];"
                             : "=r"(b0), "=r"(b1) : "r"(baddr));
                asm volatile("mma.sync.aligned.m16n8k16.row.col.f32.bf16.bf16.f32 "
                             "{%0,%1,%2,%3}, {%4,%5,%6,%7}, {%8,%9}, {%0,%1,%2,%3};"
                             : "+f"(acc[j][0]), "+f"(acc[j][1]), "+f"(acc[j][2]), "+f"(acc[j][3])
                             : "r"(a0), "r"(a1), "r"(a2), "r"(a3), "r"(b0), "r"(b1));
            }
        }

        // D frag: d0,d1 -> row msub+g cols tig*2(+1); d2,d3 -> row msub+g+8
        #pragma unroll
        for (int j = 0; j < 8; j++) {
            int idb = nbase + nhalf * 64 + j * 8 + (lane & 3) * 2;
            if (acc[j][0] > tv[0][7]) ins8(tv[0], ti[0], acc[j][0], idb);
            if (acc[j][1] > tv[0][7]) ins8(tv[0], ti[0], acc[j][1], idb + 1);
            if (acc[j][2] > tv[1][7]) ins8(tv[1], ti[1], acc[j][2], idb);
            if (acc[j][3] > tv[1][7]) ins8(tv[1], ti[1], acc[j][3], idb + 1);
        }
    }

    // merge across the 4 lanes (tig) sharing each row
    #pragma unroll
    for (int step = 1; step <= 2; step <<= 1) {
        #pragma unroll
        for (int r = 0; r < 2; r++) {
            float ov[8]; int oi[8];
            #pragma unroll
            for (int s = 0; s < 8; s++) {
                ov[s] = __shfl_xor_sync(0xffffffffu, tv[r][s], step);
                oi[s] = __shfl_xor_sync(0xffffffffu, ti[r][s], step);
            }
            #pragma unroll
            for (int s = 0; s < 8; s++)
                if (ov[s] > tv[r][7]) ins8(tv[r], ti[r], ov[s], oi[s]);
        }
    }

    if ((lane & 3) == 0) {
        int g = lane >> 2;
        int row0 = m0 + msub + g;
        int row1 = row0 + 8;
        // per-(row, split, half) slot: no races between nhalf=0 and nhalf=1
        int base0 = ((row0 * 8 + blockIdx.y) * 2 + nhalf) * 8;
        int base1 = ((row1 * 8 + blockIdx.y) * 2 + nhalf) * 8;
        #pragma unroll
        for (int s = 0; s < 8; s++) {
            pidx[base0 + s] = ti[0][s];
            pidx[base1 + s] = ti[1][s];
        }
    }
}

// ===== exact fp32 rescore of 128 candidates/row -> top-4 -> gather -> v_combined =====
__global__ void rescore_kernel(const float* __restrict__ Q, const float* __restrict__ KN,
                               const int* __restrict__ pidx,
                               const float* __restrict__ cvals, const float* __restrict__ vmem,
                               float* __restrict__ vc)
{
    int b = blockIdx.x;
    int t = threadIdx.x;          // 128 threads
    __shared__ float qrow[64];
    __shared__ float vals[128];
    __shared__ int   ids[128];
    __shared__ int   sidx[4];
    if (t < 64) qrow[t] = Q[b * 64 + t];
    __syncthreads();
    int id = pidx[b * 128 + t];
    const float4* kr = (const float4*)(KN + (size_t)id * 64);
    const float4* q4 = (const float4*)qrow;
    float s = 0.f;
    #pragma unroll
    for (int j = 0; j < 16; j++) {
        float4 kv = kr[j];
        float4 qv = q4[j];
        s += qv.x * kv.x + qv.y * kv.y + qv.z * kv.z + qv.w * kv.w;
    }
    vals[t] = s; ids[t] = id;
    __syncthreads();
    if (t == 0) {
        float bv[4] = {NEG, NEG, NEG, NEG};
        int bi[4] = {0x7FFFFFFF, 0x7FFFFFFF, 0x7FFFFFFF, 0x7FFFFFFF};
        for (int j = 0; j < 128; j++) ins4(bv, bi, vals[j], ids[j]);
        sidx[0]=bi[0]; sidx[1]=bi[1]; sidx[2]=bi[2]; sidx[3]=bi[3];
    }
    __syncthreads();
    if (t < 64) {
        float sum = cvals[(size_t)sidx[0] * 64 + t] + cvals[(size_t)sidx[1] * 64 + t]
                  + cvals[(size_t)sidx[2] * 64 + t] + cvals[(size_t)sidx[3] * 64 + t];
        vc[b * 64 + t] = 0.5f * (vmem[b * 64 + t] + sum * 0.25f);
    }
}

__global__ void cf_partial_kernel(const float* __restrict__ z1, const float* __restrict__ z2,
                                  const float* __restrict__ z, const float* __restrict__ vc,
                                  float* __restrict__ part)
{
    __shared__ float red[256];
    float s = 0.f;
    for (int i = blockIdx.x * 256 + threadIdx.x; i < BB * DD; i += 256 * 256) {
        float d = 0.5f * (z1[i] + z2[i]) - z[i] - vc[i];
        s += d * d;
    }
    red[threadIdx.x] = s;
    __syncthreads();
    for (int st = 128; st > 0; st >>= 1) {
        if (threadIdx.x < st) red[threadIdx.x] += red[threadIdx.x + st];
        __syncthreads();
    }
    if (threadIdx.x == 0) part[blockIdx.x] = red[0];
}

__global__ void cf_final_kernel(const float* __restrict__ part, float* __restrict__ out)
{
    __shared__ float red[256];
    red[threadIdx.x] = part[threadIdx.x];
    __syncthreads();
    for (int st = 128; st > 0; st >>= 1) {
        if (threadIdx.x < st) red[threadIdx.x] += red[threadIdx.x + st];
        __syncthreads();
    }
    if (threadIdx.x == 0) out[BB * DD] = red[0] * (1.0f / (float)(BB * DD));
}

extern "C" void kernel_launch(void* const* d_in, const int* in_sizes, int n_in,
                              void* d_out, int out_size)
{
    const float* z    = (const float*)d_in[0];
    const float* hot  = (const float*)d_in[2];
    const float* gap  = (const float*)d_in[3];
    const float* Wq   = (const float*)d_in[4];
    const float* bq   = (const float*)d_in[5];
    const float* Wf   = (const float*)d_in[6];
    const float* bf   = (const float*)d_in[7];
    const float* mem  = (const float*)d_in[8];
    const float* Wk   = (const float*)d_in[9];
    const float* Wo   = (const float*)d_in[10];
    const float* ck   = (const float*)d_in[11];
    const float* cvals= (const float*)d_in[12];
    const float* aemb = (const float*)d_in[13];
    const float* Wih  = (const float*)d_in[14];
    const float* Whh  = (const float*)d_in[15];
    const float* bih  = (const float*)d_in[16];
    const float* bhh  = (const float*)d_in[17];
    const float* h0   = (const float*)d_in[18];
    const float* Wo1  = (const float*)d_in[19];
    const float* bo1  = (const float*)d_in[20];
    const float* Wo2  = (const float*)d_in[21];
    const float* bo2  = (const float*)d_in[22];
    const int*   acts = (const int*)d_in[23];
    float* out = (float*)d_out;

    float* scr = nullptr;
    cudaGetSymbolAddress((void**)&scr, d_scr);
    __nv_bfloat16* Qh  = (__nv_bfloat16*)(scr + OFF_QH);
    __nv_bfloat16* KNh = (__nv_bfloat16*)(scr + OFF_KNH);

    // tensor-product memory folded to 64x64 A
    prepA_kernel<<<8, 256>>>(mem, Wk, Wo, scr + OFF_APART);
    reduceAT_kernel<<<16, 256>>>(scr + OFF_APART, scr + OFF_AT);

    // query = (z*hot)@Wq^T + bq (premul fused; bf16 mirror for HMMA screen)
    gemm_kernel<<<dim3(64, 1), 256>>>(z, hot, Wq, bq, scr + OFF_Q, 64, 64, 0, Qh);
    normalize_rows_kernel<<<2048, 256>>>(ck, scr + OFF_KN, KNh);
    gemm_kernel<<<dim3(64, 1), 256>>>(scr + OFF_Q, nullptr, scr + OFF_AT, scr + OFF_ZERO,
                                      scr + OFF_VMEM, 64, 64, 0, nullptr);

    // episodic recall: bf16 HMMA screen (top-8 per row/split/half) + exact fp32 rescore
    mma_sims_kernel<<<dim3(64, 8), 256>>>(Qh, KNh, (int*)(scr + OFF_PIDX));
    rescore_kernel<<<BB, 128>>>(scr + OFF_Q, scr + OFF_KN, (int*)(scr + OFF_PIDX),
                                cvals, scr + OFF_VMEM, scr + OFF_VC);

    // GRU rollout, T=2; GH(t=0) collapses to a 384-vector
    gh0_kernel<<<48, 256>>>(h0, Whh, bhh, scr + OFF_GH0);
    // t = 0
    buildx_kernel<<<2048, 256>>>(z, aemb, acts, 0, scr + OFF_X);
    gemm_kernel<<<dim3(64, 6), 256>>>(scr + OFF_X, nullptr, Wih, bih, scr + OFF_GI, 384, 128, 0, nullptr);
    gates0_kernel<<<2048, 256>>>(scr + OFF_GI, scr + OFF_GH0, h0, scr + OFF_H2A);
    gemm_kernel<<<dim3(64, 2), 256>>>(scr + OFF_H2A, nullptr, Wo1, bo1, scr + OFF_HID, 128, 128, 1, nullptr);
    gemm_kernel<<<dim3(64, 1), 256>>>(scr + OFF_HID, nullptr, Wo2, bo2, scr + OFF_Z1, 64, 128, 0, nullptr);
    // t = 1
    buildx_kernel<<<2048, 256>>>(scr + OFF_Z1, aemb, acts, 1, scr + OFF_X);
    gemm_kernel<<<dim3(64, 6), 256>>>(scr + OFF_X, nullptr, Wih, bih, scr + OFF_GI, 384, 128, 0, nullptr);
    gemm_kernel<<<dim3(64, 6), 256>>>(scr + OFF_H2A, nullptr, Whh, bhh, scr + OFF_GH, 384, 128, 0, nullptr);
    gates_kernel<<<2048, 256>>>(scr + OFF_GI, scr + OFF_GH, scr + OFF_H2A, scr + OFF_H2B);
    gemm_kernel<<<dim3(64, 2), 256>>>(scr + OFF_H2B, nullptr, Wo1, bo1, scr + OFF_HID, 128, 128, 1, nullptr);
    gemm_kernel<<<dim3(64, 1), 256>>>(scr + OFF_HID, nullptr, Wo2, bo2, scr + OFF_Z2, 64, 128, 0, nullptr);

    // cf loss
    cf_partial_kernel<<<256, 256>>>(scr + OFF_Z1, scr + OFF_Z2, z, scr + OFF_VC, scr + OFF_CFP);
    cf_final_kernel<<<1, 256>>>(scr + OFF_CFP, out);

    // fused fusion + masked select
    fuse2_kernel<<<64, 256>>>(z, scr + OFF_VC, Wf, bf, gap, out);
}

// round 8
// speedup vs baseline: 1.9051x; 1.0025x over previous
#include <cuda_runtime.h>
#include <cuda_bf16.h>
#include <cstdint>

#define BB 4096
#define DD 64
#define HH8 8
#define CC 16384
#define TAU 0.3f
#define NEG (-1e30f)

// ---- scratch offsets (floats) ----
constexpr int OFF_AT    = 0;
constexpr int OFF_APART = OFF_AT    + 4096;
constexpr int OFF_KN    = OFF_APART + 32768;
constexpr int OFF_Q     = OFF_KN    + 1048576;
constexpr int OFF_VC    = OFF_Q     + 262144;
constexpr int OFF_PIDX  = OFF_VC    + 262144;   // 4096*8*16 ints
constexpr int OFF_QH    = OFF_PIDX  + 524288;   // 4096*64 bf16
constexpr int OFF_KNH   = OFF_QH    + 131072;   // 16384*64 bf16
constexpr int OFF_GI    = OFF_KNH   + 524288;
constexpr int OFF_GH    = OFF_GI    + 1572864;
constexpr int OFF_H2A   = OFF_GH    + 1572864;
constexpr int OFF_H2B   = OFF_H2A   + 524288;
constexpr int OFF_HID   = OFF_H2B   + 524288;
constexpr int OFF_Z1    = OFF_HID   + 524288;
constexpr int OFF_Z2    = OFF_Z1    + 262144;
constexpr int OFF_GH0   = OFF_Z2    + 262144;   // 512
constexpr int OFF_CFP   = OFF_GH0   + 512;      // 256
constexpr int OFF_ZERO  = OFF_CFP   + 256;      // 512 zeros
constexpr int SCR_TOTAL = OFF_ZERO  + 512;

__device__ float d_scr[SCR_TOTAL];

#define BETTER(v,id,V,I) ((v) > (V) || ((v) == (V) && (id) < (I)))

__device__ __forceinline__ void ins4(float (&tv)[4], int (&ti)[4], float v, int id) {
    if (BETTER(v, id, tv[3], ti[3])) {
        if (BETTER(v, id, tv[0], ti[0])) {
            tv[3]=tv[2]; ti[3]=ti[2]; tv[2]=tv[1]; ti[2]=ti[1];
            tv[1]=tv[0]; ti[1]=ti[0]; tv[0]=v; ti[0]=id;
        } else if (BETTER(v, id, tv[1], ti[1])) {
            tv[3]=tv[2]; ti[3]=ti[2]; tv[2]=tv[1]; ti[2]=ti[1];
            tv[1]=v; ti[1]=id;
        } else if (BETTER(v, id, tv[2], ti[2])) {
            tv[3]=tv[2]; ti[3]=ti[2]; tv[2]=v; ti[2]=id;
        } else {
            tv[3]=v; ti[3]=id;
        }
    }
}

// top-8 insertion (candidate-set membership; exact order fixed by fp32 rescore)
__device__ __forceinline__ void ins8(float (&tv)[8], int (&ti)[8], float v, int id) {
    if (!(v > tv[7])) return;
    #pragma unroll
    for (int s = 7; s >= 1; s--) {
        if (v > tv[s-1])      { tv[s] = tv[s-1]; ti[s] = ti[s-1]; }
        else if (v > tv[s])   { tv[s] = v;       ti[s] = id;      }
    }
    if (v > tv[0]) { tv[0] = v; ti[0] = id; }
}

__device__ __forceinline__ uint32_t smem_u32(const void* p) {
    uint32_t a;
    asm("{ .reg .u64 t; cvta.to.shared.u64 t, %1; cvt.u32.u64 %0, t; }" : "=r"(a) : "l"(p));
    return a;
}
#define SW128(o) ((o) ^ (((o) >> 3) & 0x70))

// ======================= prep kernels =======================
__global__ void prepA_kernel(const float* __restrict__ mem,
                             const float* __restrict__ Wk,
                             const float* __restrict__ Wo,
                             float* __restrict__ Apart)
{
    int h = blockIdx.x;
    __shared__ float WoT[64 * 65];
    __shared__ float Mh[64 * 64];
    int t = threadIdx.x;
    #pragma unroll
    for (int p = 0; p < 16; p++) {
        int e = t + p * 256;
        int r = e >> 6, c = e & 63;
        WoT[c * 65 + r] = Wo[e];
    }
    __syncthreads();
    #pragma unroll
    for (int p = 0; p < 16; p++) {
        int e = t + p * 256;
        int dp = e >> 6, j = e & 63;
        const float* mrow = mem + h * 4096 + dp * 64;
        float s = 0.f;
        #pragma unroll
        for (int ee = 0; ee < 64; ee++) s += mrow[ee] * WoT[ee * 65 + j];
        Mh[dp * 64 + j] = s;
    }
    __syncthreads();
    #pragma unroll
    for (int p = 0; p < 16; p++) {
        int e = t + p * 256;
        int i = e >> 6, j = e & 63;
        float s = 0.f;
        #pragma unroll
        for (int dp = 0; dp < 64; dp++)
            s += Wk[(h * 64 + dp) * 64 + i] * Mh[dp * 64 + j];
        Apart[h * 4096 + e] = s;
    }
}

__global__ void reduceAT_kernel(const float* __restrict__ Apart,
                                float* __restrict__ AT)
{
    int e = blockIdx.x * 256 + threadIdx.x;
    int i = e >> 6, j = e & 63;
    float s = 0.f;
    #pragma unroll
    for (int h = 0; h < HH8; h++) s += Apart[h * 4096 + e];
    AT[j * 64 + i] = s * 0.125f;     // AT[j][i] = mean_h A[i][j]
}

// normalize cache keys; emit fp32 (rescore) + bf16 (tensor-core) copies
__global__ void normalize_rows_kernel(const float* __restrict__ src,
                                      float* __restrict__ dst,
                                      __nv_bfloat16* __restrict__ dsth)
{
    int row  = blockIdx.x * 8 + (threadIdx.x >> 5);
    int lane = threadIdx.x & 31;
    float a = src[row * 64 + lane];
    float b = src[row * 64 + 32 + lane];
    float ss = a * a + b * b;
    #pragma unroll
    for (int off = 16; off > 0; off >>= 1)
        ss += __shfl_xor_sync(0xffffffffu, ss, off);
    float inv = 1.0f / fmaxf(sqrtf(ss), 1e-8f);
    float na = a * inv, nb = b * inv;
    dst[row * 64 + lane]       = na;
    dst[row * 64 + 32 + lane]  = nb;
    dsth[row * 64 + lane]      = __float2bfloat16(na);
    dsth[row * 64 + 32 + lane] = __float2bfloat16(nb);
}

__global__ void gh0_kernel(const float* __restrict__ h0, const float* __restrict__ Whh,
                           const float* __restrict__ bhh, float* __restrict__ gh0)
{
    int w = blockIdx.x * 8 + (threadIdx.x >> 5);
    int lane = threadIdx.x & 31;
    const float* row = Whh + w * 128;
    float s = row[lane] * h0[lane] + row[lane + 32] * h0[lane + 32]
            + row[lane + 64] * h0[lane + 64] + row[lane + 96] * h0[lane + 96];
    #pragma unroll
    for (int off = 16; off > 0; off >>= 1)
        s += __shfl_xor_sync(0xffffffffu, s, off);
    if (lane == 0) gh0[w] = s + bhh[w];
}

__global__ void gates0_kernel(const float* __restrict__ gi, const float* __restrict__ gh0,
                              const float* __restrict__ h0, float* __restrict__ h2)
{
    int i = blockIdx.x * 256 + threadIdx.x;
    int b = i >> 7, j = i & 127;
    const float* gib = gi + b * 384;
    float r = 1.0f / (1.0f + expf(-(gib[j] + gh0[j])));
    float u = 1.0f / (1.0f + expf(-(gib[128 + j] + gh0[128 + j])));
    float n = tanhf(gib[256 + j] + r * gh0[256 + j]);
    float h = h0[j];
    h2[i] = (1.0f - u) * n + u * h;
}

__global__ void gates_kernel(const float* __restrict__ gi, const float* __restrict__ gh,
                             const float* __restrict__ hprev, float* __restrict__ h2)
{
    int i = blockIdx.x * 256 + threadIdx.x;
    int b = i >> 7, j = i & 127;
    const float* gib = gi + b * 384;
    const float* ghb = gh + b * 384;
    float r = 1.0f / (1.0f + expf(-(gib[j] + ghb[j])));
    float u = 1.0f / (1.0f + expf(-(gib[128 + j] + ghb[128 + j])));
    float n = tanhf(gib[256 + j] + r * ghb[256 + j]);
    float h = hprev[i];
    h2[i] = (1.0f - u) * n + u * h;
}

// ---- tiled GEMM: C = act((A?P) @ W^T + bias); optional bf16 mirror ----
__global__ __launch_bounds__(256) void gemm_kernel(
    const float* __restrict__ A, const float* __restrict__ P,
    const float* __restrict__ W, const float* __restrict__ bias,
    float* __restrict__ Cm, int N, int K, int act,
    __nv_bfloat16* __restrict__ Ch)
{
    __shared__ float As[16 * 68];
    __shared__ float Ws[16 * 68];
    int tid = threadIdx.x;
    int tx = tid & 15, ty = tid >> 4;
    int m0 = blockIdx.x * 64, n0 = blockIdx.y * 64;
    float acc[16];
    #pragma unroll
    for (int q = 0; q < 16; q++) acc[q] = 0.f;
    int li = tid >> 2;
    int lj = (tid & 3) * 4;
    for (int kt = 0; kt < K; kt += 16) {
        float4 av = *(const float4*)(A + (size_t)(m0 + li) * K + kt + lj);
        if (P) {
            float4 pv = *(const float4*)(P + (size_t)(m0 + li) * K + kt + lj);
            av.x *= pv.x; av.y *= pv.y; av.z *= pv.z; av.w *= pv.w;
        }
        float4 wv = *(const float4*)(W + (size_t)(n0 + li) * K + kt + lj);
        As[(lj + 0) * 68 + li] = av.x; As[(lj + 1) * 68 + li] = av.y;
        As[(lj + 2) * 68 + li] = av.z; As[(lj + 3) * 68 + li] = av.w;
        Ws[(lj + 0) * 68 + li] = wv.x; Ws[(lj + 1) * 68 + li] = wv.y;
        Ws[(lj + 2) * 68 + li] = wv.z; Ws[(lj + 3) * 68 + li] = wv.w;
        __syncthreads();
        #pragma unroll
        for (int k = 0; k < 16; k++) {
            float4 a = *(const float4*)(As + k * 68 + ty * 4);
            float4 b = *(const float4*)(Ws + k * 68 + tx * 4);
            acc[0]+=a.x*b.x; acc[1]+=a.x*b.y; acc[2]+=a.x*b.z; acc[3]+=a.x*b.w;
            acc[4]+=a.y*b.x; acc[5]+=a.y*b.y; acc[6]+=a.y*b.z; acc[7]+=a.y*b.w;
            acc[8]+=a.z*b.x; acc[9]+=a.z*b.y; acc[10]+=a.z*b.z; acc[11]+=a.z*b.w;
            acc[12]+=a.w*b.x; acc[13]+=a.w*b.y; acc[14]+=a.w*b.z; acc[15]+=a.w*b.w;
        }
        __syncthreads();
    }
    float4 bs = *(const float4*)(bias + n0 + tx * 4);
    float bcol[4] = {bs.x, bs.y, bs.z, bs.w};
    #pragma unroll
    for (int rr = 0; rr < 4; rr++) {
        int m = m0 + ty * 4 + rr;
        float4 o;
        float* op = (float*)&o;
        #pragma unroll
        for (int cc = 0; cc < 4; cc++) {
            float v = acc[rr * 4 + cc] + bcol[cc];
            if (act == 1) v = 0.5f * v * (1.0f + erff(v * 0.70710678118654752f));
            op[cc] = v;
        }
        *(float4*)(Cm + (size_t)m * N + n0 + tx * 4) = o;
        if (Ch) {
            #pragma unroll
            for (int cc = 0; cc < 4; cc++)
                Ch[(size_t)m * N + n0 + tx * 4 + cc] = __float2bfloat16(op[cc]);
        }
    }
}

// ---- GI GEMM with gathered A = [zprev | aemb[actions[:,t]]] (K=128) ----
__global__ __launch_bounds__(256) void gi_gemm_kernel(
    const float* __restrict__ zprev, const float* __restrict__ aemb,
    const int* __restrict__ actions, int t,
    const float* __restrict__ W, const float* __restrict__ bias,
    float* __restrict__ Cm, int N)
{
    __shared__ float As[16 * 68];
    __shared__ float Ws[16 * 68];
    __shared__ int aidx[64];
    int tid = threadIdx.x;
    int tx = tid & 15, ty = tid >> 4;
    int m0 = blockIdx.x * 64, n0 = blockIdx.y * 64;
    if (tid < 64) aidx[tid] = actions[(m0 + tid) * 2 + t];
    float acc[16];
    #pragma unroll
    for (int q = 0; q < 16; q++) acc[q] = 0.f;
    int li = tid >> 2;
    int lj = (tid & 3) * 4;
    __syncthreads();
    for (int kt = 0; kt < 128; kt += 16) {
        float4 av;
        if (kt < 64) av = *(const float4*)(zprev + (size_t)(m0 + li) * 64 + kt + lj);
        else         av = *(const float4*)(aemb + (size_t)aidx[li] * 64 + (kt - 64) + lj);
        float4 wv = *(const float4*)(W + (size_t)(n0 + li) * 128 + kt + lj);
        As[(lj + 0) * 68 + li] = av.x; As[(lj + 1) * 68 + li] = av.y;
        As[(lj + 2) * 68 + li] = av.z; As[(lj + 3) * 68 + li] = av.w;
        Ws[(lj + 0) * 68 + li] = wv.x; Ws[(lj + 1) * 68 + li] = wv.y;
        Ws[(lj + 2) * 68 + li] = wv.z; Ws[(lj + 3) * 68 + li] = wv.w;
        __syncthreads();
        #pragma unroll
        for (int k = 0; k < 16; k++) {
            float4 a = *(const float4*)(As + k * 68 + ty * 4);
            float4 b = *(const float4*)(Ws + k * 68 + tx * 4);
            acc[0]+=a.x*b.x; acc[1]+=a.x*b.y; acc[2]+=a.x*b.z; acc[3]+=a.x*b.w;
            acc[4]+=a.y*b.x; acc[5]+=a.y*b.y; acc[6]+=a.y*b.z; acc[7]+=a.y*b.w;
            acc[8]+=a.z*b.x; acc[9]+=a.z*b.y; acc[10]+=a.z*b.z; acc[11]+=a.z*b.w;
            acc[12]+=a.w*b.x; acc[13]+=a.w*b.y; acc[14]+=a.w*b.z; acc[15]+=a.w*b.w;
        }
        __syncthreads();
    }
    float4 bs = *(const float4*)(bias + n0 + tx * 4);
    float bcol[4] = {bs.x, bs.y, bs.z, bs.w};
    #pragma unroll
    for (int rr = 0; rr < 4; rr++) {
        int m = m0 + ty * 4 + rr;
        float4 o;
        float* op = (float*)&o;
        #pragma unroll
        for (int cc = 0; cc < 4; cc++) op[cc] = acc[rr * 4 + cc] + bcol[cc];
        *(float4*)(Cm + (size_t)m * N + n0 + tx * 4) = o;
    }
}

// ---- fused fusion+select ----
__global__ __launch_bounds__(256) void fuse2_kernel(
    const float* __restrict__ z, const float* __restrict__ vc,
    const float* __restrict__ Wf, const float* __restrict__ bf,
    const float* __restrict__ gap, float* __restrict__ out)
{
    __shared__ float As[16 * 68];
    __shared__ float Ws[16 * 68];
    int tid = threadIdx.x;
    int tx = tid & 15, ty = tid >> 4;
    int m0 = blockIdx.x * 64;
    float acc[16];
    #pragma unroll
    for (int q = 0; q < 16; q++) acc[q] = 0.f;
    int li = tid >> 2;
    int lj = (tid & 3) * 4;
    for (int kt = 0; kt < 128; kt += 16) {
        const float* src = (kt < 64) ? (z + (size_t)(m0 + li) * 64 + kt + lj)
                                     : (vc + (size_t)(m0 + li) * 64 + (kt - 64) + lj);
        float4 av = *(const float4*)src;
        float4 wv = *(const float4*)(Wf + (size_t)li * 128 + kt + lj);
        As[(lj + 0) * 68 + li] = av.x; As[(lj + 1) * 68 + li] = av.y;
        As[(lj + 2) * 68 + li] = av.z; As[(lj + 3) * 68 + li] = av.w;
        Ws[(lj + 0) * 68 + li] = wv.x; Ws[(lj + 1) * 68 + li] = wv.y;
        Ws[(lj + 2) * 68 + li] = wv.z; Ws[(lj + 3) * 68 + li] = wv.w;
        __syncthreads();
        #pragma unroll
        for (int k = 0; k < 16; k++) {
            float4 a = *(const float4*)(As + k * 68 + ty * 4);
            float4 b = *(const float4*)(Ws + k * 68 + tx * 4);
            acc[0]+=a.x*b.x; acc[1]+=a.x*b.y; acc[2]+=a.x*b.z; acc[3]+=a.x*b.w;
            acc[4]+=a.y*b.x; acc[5]+=a.y*b.y; acc[6]+=a.y*b.z; acc[7]+=a.y*b.w;
            acc[8]+=a.z*b.x; acc[9]+=a.z*b.y; acc[10]+=a.z*b.z; acc[11]+=a.z*b.w;
            acc[12]+=a.w*b.x; acc[13]+=a.w*b.y; acc[14]+=a.w*b.z; acc[15]+=a.w*b.w;
        }
        __syncthreads();
    }
    float4 bs = *(const float4*)(bf + tx * 4);
    float bcol[4] = {bs.x, bs.y, bs.z, bs.w};
    #pragma unroll
    for (int rr = 0; rr < 4; rr++) {
        int m = m0 + ty * 4 + rr;
        bool act = gap[m] > TAU;
        float4 o;
        float* op = (float*)&o;
        #pragma unroll
        for (int cc = 0; cc < 4; cc++) {
            float v = acc[rr * 4 + cc] + bcol[cc];
            op[cc] = act ? v : z[(size_t)m * 64 + tx * 4 + cc];
        }
        *(float4*)(out + (size_t)m * 64 + tx * 4) = o;
    }
}

// =============== HMMA sims screen: bf16 mma.sync + per-row top-8 ===============
// grid (64 m-tiles, 8 splits), 256 threads = 8 warps.
// Warp w: rows msub=(w&3)*16, key-half nhalf=w>>2. B loaded via ldmatrix.x4
// (two j-blocks per load). Each (row, split, half) owns its pidx slot.
__global__ __launch_bounds__(256) void mma_sims_kernel(
    const __nv_bfloat16* __restrict__ Qh,
    const __nv_bfloat16* __restrict__ KNh,
    int* __restrict__ pidx)
{
    __shared__ __align__(1024) char sm[8192 + 16384];
    const uint32_t QOFF = 0, KOFF = 8192;
    uint32_t smb = smem_u32(sm);
    int tid = threadIdx.x;
    int warp = tid >> 5, lane = tid & 31;
    int msub = (warp & 3) * 16;
    int nhalf = warp >> 2;
    int m0 = blockIdx.x * 64;
    int c0 = blockIdx.y * 2048;

    // Q tile: 64 rows x 64 bf16 (128B rows, SW128)
    #pragma unroll
    for (int p = 0; p < 2; p++) {
        int c = tid + p * 256;
        int row = c >> 3, kc = c & 7;
        uint4 v = *(const uint4*)(Qh + (size_t)(m0 + row) * 64 + kc * 8);
        *(uint4*)(sm + QOFF + SW128((uint32_t)(row * 128 + kc * 16))) = v;
    }

    float tv[2][8]; int ti[2][8];
    #pragma unroll
    for (int r = 0; r < 2; r++)
        #pragma unroll
        for (int s = 0; s < 8; s++) { tv[r][s] = NEG; ti[r][s] = 0x7FFFFFFF; }

    for (int it = 0; it < 16; it++) {
        int nbase = c0 + it * 128;
        __syncthreads();
        #pragma unroll
        for (int p = 0; p < 4; p++) {
            int c = tid + p * 256;
            int row = c >> 3, kc = c & 7;
            uint4 v = *(const uint4*)(KNh + (size_t)(nbase + row) * 64 + kc * 8);
            *(uint4*)(sm + KOFF + SW128((uint32_t)(row * 128 + kc * 16))) = v;
        }
        __syncthreads();

        float acc[8][4];
        #pragma unroll
        for (int j = 0; j < 8; j++)
            #pragma unroll
            for (int q = 0; q < 4; q++) acc[j][q] = 0.f;

        #pragma unroll
        for (int kk = 0; kk < 4; kk++) {
            uint32_t a0, a1, a2, a3;
            uint32_t aaddr = smb + QOFF +
                SW128((uint32_t)((msub + (lane & 15)) * 128 + kk * 32 + (lane >> 4) * 16));
            asm volatile("ldmatrix.sync.aligned.m8n8.x4.shared.b16 {%0,%1,%2,%3}, [%4];"
                         : "=r"(a0), "=r"(a1), "=r"(a2), "=r"(a3) : "r"(aaddr));
            #pragma unroll
            for (int j2 = 0; j2 < 4; j2++) {
                // x4 B: mats 0/1 = keys j2*16+0..7 (k lo/hi); mats 2/3 = keys +8..15
                int keyrow = nhalf * 64 + j2 * 16 + ((lane >> 4) * 8) + (lane & 7);
                uint32_t baddr = smb + KOFF +
                    SW128((uint32_t)(keyrow * 128 + kk * 32 + ((lane >> 3) & 1) * 16));
                uint32_t b0, b1, b2, b3;
                asm volatile("ldmatrix.sync.aligned.m8n8.x4.shared.b16 {%0,%1,%2,%3}, [%4];"
                             : "=r"(b0), "=r"(b1), "=r"(b2), "=r"(b3) : "r"(baddr));
                int j = j2 * 2;
                asm volatile("mma.sync.aligned.m16n8k16.row.col.f32.bf16.bf16.f32 "
                             "{%0,%1,%2,%3}, {%4,%5,%6,%7}, {%8,%9}, {%0,%1,%2,%3};"
                             : "+f"(acc[j][0]), "+f"(acc[j][1]), "+f"(acc[j][2]), "+f"(acc[j][3])
                             : "r"(a0), "r"(a1), "r"(a2), "r"(a3), "r"(b0), "r"(b1));
                asm volatile("mma.sync.aligned.m16n8k16.row.col.f32.bf16.bf16.f32 "
                             "{%0,%1,%2,%3}, {%4,%5,%6,%7}, {%8,%9}, {%0,%1,%2,%3};"
                             : "+f"(acc[j+1][0]), "+f"(acc[j+1][1]), "+f"(acc[j+1][2]), "+f"(acc[j+1][3])
                             : "r"(a0), "r"(a1), "r"(a2), "r"(a3), "r"(b2), "r"(b3));
            }
        }

        #pragma unroll
        for (int j = 0; j < 8; j++) {
            int idb = nbase + nhalf * 64 + j * 8 + (lane & 3) * 2;
            if (acc[j][0] > tv[0][7]) ins8(tv[0], ti[0], acc[j][0], idb);
            if (acc[j][1] > tv[0][7]) ins8(tv[0], ti[0], acc[j][1], idb + 1);
            if (acc[j][2] > tv[1][7]) ins8(tv[1], ti[1], acc[j][2], idb);
            if (acc[j][3] > tv[1][7]) ins8(tv[1], ti[1], acc[j][3], idb + 1);
        }
    }

    // merge across the 4 lanes (tig) sharing each row
    #pragma unroll
    for (int step = 1; step <= 2; step <<= 1) {
        #pragma unroll
        for (int r = 0; r < 2; r++) {
            float ov[8]; int oi[8];
            #pragma unroll
            for (int s = 0; s < 8; s++) {
                ov[s] = __shfl_xor_sync(0xffffffffu, tv[r][s], step);
                oi[s] = __shfl_xor_sync(0xffffffffu, ti[r][s], step);
            }
            #pragma unroll
            for (int s = 0; s < 8; s++)
                if (ov[s] > tv[r][7]) ins8(tv[r], ti[r], ov[s], oi[s]);
        }
    }

    if ((lane & 3) == 0) {
        int g = lane >> 2;
        int row0 = m0 + msub + g;
        int row1 = row0 + 8;
        int base0 = ((row0 * 8 + blockIdx.y) * 2 + nhalf) * 8;
        int base1 = ((row1 * 8 + blockIdx.y) * 2 + nhalf) * 8;
        #pragma unroll
        for (int s = 0; s < 8; s++) {
            pidx[base0 + s] = ti[0][s];
            pidx[base1 + s] = ti[1][s];
        }
    }
}

// ===== rescore 128 candidates/row (fp32) -> top-4 -> gather; vmem computed inline =====
__global__ void rescore_kernel(const float* __restrict__ Q, const float* __restrict__ KN,
                               const int* __restrict__ pidx, const float* __restrict__ AT,
                               const float* __restrict__ cvals, float* __restrict__ vc)
{
    int b = blockIdx.x;
    int t = threadIdx.x;          // 128 threads
    __shared__ float qrow[64];
    __shared__ float vals[128];
    __shared__ int   ids[128];
    __shared__ int   sidx[4];
    if (t < 64) qrow[t] = Q[b * 64 + t];
    __syncthreads();
    int id = pidx[b * 128 + t];
    const float4* kr = (const float4*)(KN + (size_t)id * 64);
    const float4* q4 = (const float4*)qrow;
    float s = 0.f;
    #pragma unroll
    for (int j = 0; j < 16; j++) {
        float4 kv = kr[j];
        float4 qv = q4[j];
        s += qv.x * kv.x + qv.y * kv.y + qv.z * kv.z + qv.w * kv.w;
    }
    vals[t] = s; ids[t] = id;
    __syncthreads();
    if (t == 0) {
        float bv[4] = {NEG, NEG, NEG, NEG};
        int bi[4] = {0x7FFFFFFF, 0x7FFFFFFF, 0x7FFFFFFF, 0x7FFFFFFF};
        for (int j = 0; j < 128; j++) ins4(bv, bi, vals[j], ids[j]);
        sidx[0]=bi[0]; sidx[1]=bi[1]; sidx[2]=bi[2]; sidx[3]=bi[3];
    }
    __syncthreads();
    if (t < 64) {
        // vmem[b][t] = sum_i qrow[i] * AT[t*64+i]
        const float4* ar = (const float4*)(AT + (size_t)t * 64);
        float vm = 0.f;
        #pragma unroll
        for (int j = 0; j < 16; j++) {
            float4 av = ar[j];
            float4 qv = q4[j];
            vm += qv.x * av.x + qv.y * av.y + qv.z * av.z + qv.w * av.w;
        }
        float sum = cvals[(size_t)sidx[0] * 64 + t] + cvals[(size_t)sidx[1] * 64 + t]
                  + cvals[(size_t)sidx[2] * 64 + t] + cvals[(size_t)sidx[3] * 64 + t];
        vc[b * 64 + t] = 0.5f * (vm + sum * 0.25f);
    }
}

__global__ void cf_partial_kernel(const float* __restrict__ z1, const float* __restrict__ z2,
                                  const float* __restrict__ z, const float* __restrict__ vc,
                                  float* __restrict__ part)
{
    __shared__ float red[256];
    float s = 0.f;
    for (int i = blockIdx.x * 256 + threadIdx.x; i < BB * DD; i += 256 * 256) {
        float d = 0.5f * (z1[i] + z2[i]) - z[i] - vc[i];
        s += d * d;
    }
    red[threadIdx.x] = s;
    __syncthreads();
    for (int st = 128; st > 0; st >>= 1) {
        if (threadIdx.x < st) red[threadIdx.x] += red[threadIdx.x + st];
        __syncthreads();
    }
    if (threadIdx.x == 0) part[blockIdx.x] = red[0];
}

__global__ void cf_final_kernel(const float* __restrict__ part, float* __restrict__ out)
{
    __shared__ float red[256];
    red[threadIdx.x] = part[threadIdx.x];
    __syncthreads();
    for (int st = 128; st > 0; st >>= 1) {
        if (threadIdx.x < st) red[threadIdx.x] += red[threadIdx.x + st];
        __syncthreads();
    }
    if (threadIdx.x == 0) out[BB * DD] = red[0] * (1.0f / (float)(BB * DD));
}

extern "C" void kernel_launch(void* const* d_in, const int* in_sizes, int n_in,
                              void* d_out, int out_size)
{
    const float* z    = (const float*)d_in[0];
    const float* hot  = (const float*)d_in[2];
    const float* gap  = (const float*)d_in[3];
    const float* Wq   = (const float*)d_in[4];
    const float* bq   = (const float*)d_in[5];
    const float* Wf   = (const float*)d_in[6];
    const float* bf   = (const float*)d_in[7];
    const float* mem  = (const float*)d_in[8];
    const float* Wk   = (const float*)d_in[9];
    const float* Wo   = (const float*)d_in[10];
    const float* ck   = (const float*)d_in[11];
    const float* cvals= (const float*)d_in[12];
    const float* aemb = (const float*)d_in[13];
    const float* Wih  = (const float*)d_in[14];
    const float* Whh  = (const float*)d_in[15];
    const float* bih  = (const float*)d_in[16];
    const float* bhh  = (const float*)d_in[17];
    const float* h0   = (const float*)d_in[18];
    const float* Wo1  = (const float*)d_in[19];
    const float* bo1  = (const float*)d_in[20];
    const float* Wo2  = (const float*)d_in[21];
    const float* bo2  = (const float*)d_in[22];
    const int*   acts = (const int*)d_in[23];
    float* out = (float*)d_out;

    float* scr = nullptr;
    cudaGetSymbolAddress((void**)&scr, d_scr);
    __nv_bfloat16* Qh  = (__nv_bfloat16*)(scr + OFF_QH);
    __nv_bfloat16* KNh = (__nv_bfloat16*)(scr + OFF_KNH);

    // ordered so mma_sims is the 4th launch (ncu anchor)
    normalize_rows_kernel<<<2048, 256>>>(ck, scr + OFF_KN, KNh);                       // 1
    gemm_kernel<<<dim3(64, 1), 256>>>(z, hot, Wq, bq, scr + OFF_Q, 64, 64, 0, Qh);     // 2
    prepA_kernel<<<8, 256>>>(mem, Wk, Wo, scr + OFF_APART);                            // 3
    mma_sims_kernel<<<dim3(64, 8), 256>>>(Qh, KNh, (int*)(scr + OFF_PIDX));            // 4
    reduceAT_kernel<<<16, 256>>>(scr + OFF_APART, scr + OFF_AT);                       // 5
    rescore_kernel<<<BB, 128>>>(scr + OFF_Q, scr + OFF_KN, (int*)(scr + OFF_PIDX),
                                scr + OFF_AT, cvals, scr + OFF_VC);                    // 6

    // GRU rollout, T=2; GH(t=0) collapses to a 384-vector
    gh0_kernel<<<48, 256>>>(h0, Whh, bhh, scr + OFF_GH0);
    // t = 0
    gi_gemm_kernel<<<dim3(64, 6), 256>>>(z, aemb, acts, 0, Wih, bih, scr + OFF_GI, 384);
    gates0_kernel<<<2048, 256>>>(scr + OFF_GI, scr + OFF_GH0, h0, scr + OFF_H2A);
    gemm_kernel<<<dim3(64, 2), 256>>>(scr + OFF_H2A, nullptr, Wo1, bo1, scr + OFF_HID, 128, 128, 1, nullptr);
    gemm_kernel<<<dim3(64, 1), 256>>>(scr + OFF_HID, nullptr, Wo2, bo2, scr + OFF_Z1, 64, 128, 0, nullptr);
    // t = 1
    gi_gemm_kernel<<<dim3(64, 6), 256>>>(scr + OFF_Z1, aemb, acts, 1, Wih, bih, scr + OFF_GI, 384);
    gemm_kernel<<<dim3(64, 6), 256>>>(scr + OFF_H2A, nullptr, Whh, bhh, scr + OFF_GH, 384, 128, 0, nullptr);
    gates_kernel<<<2048, 256>>>(scr + OFF_GI, scr + OFF_GH, scr + OFF_H2A, scr + OFF_H2B);
    gemm_kernel<<<dim3(64, 2), 256>>>(scr + OFF_H2B, nullptr, Wo1, bo1, scr + OFF_HID, 128, 128, 1, nullptr);
    gemm_kernel<<<dim3(64, 1), 256>>>(scr + OFF_HID, nullptr, Wo2, bo2, scr + OFF_Z2, 64, 128, 0, nullptr);

    // cf loss
    cf_partial_kernel<<<256, 256>>>(scr + OFF_Z1, scr + OFF_Z2, z, scr + OFF_VC, scr + OFF_CFP);
    cf_final_kernel<<<1, 256>>>(scr + OFF_CFP, out);

    // fused fusion + masked select
    fuse2_kernel<<<64, 256>>>(z, scr + OFF_VC, Wf, bf, gap, out);
}

// round 9
// speedup vs baseline: 2.6395x; 1.3855x over previous
#include <cuda_runtime.h>
#include <cuda_bf16.h>
#include <cstdint>

#define BB 4096
#define DD 64
#define HH8 8
#define CC 16384
#define TAU 0.3f
#define NEG (-1e30f)

// ---- scratch offsets (floats) ----
constexpr int OFF_AT    = 0;
constexpr int OFF_APART = OFF_AT    + 4096;
constexpr int OFF_KN    = OFF_APART + 32768;
constexpr int OFF_Q     = OFF_KN    + 1048576;
constexpr int OFF_VC    = OFF_Q     + 262144;
constexpr int OFF_PIDX  = OFF_VC    + 262144;   // 4096*8*2*4 ints = 262144
constexpr int OFF_QH    = OFF_PIDX  + 262144;   // 4096*64 bf16
constexpr int OFF_KNH   = OFF_QH    + 131072;   // 16384*64 bf16
constexpr int OFF_GI    = OFF_KNH   + 524288;
constexpr int OFF_GH    = OFF_GI    + 1572864;
constexpr int OFF_H2A   = OFF_GH    + 1572864;
constexpr int OFF_H2B   = OFF_H2A   + 524288;
constexpr int OFF_HID   = OFF_H2B   + 524288;
constexpr int OFF_Z1    = OFF_HID   + 524288;
constexpr int OFF_Z2    = OFF_Z1    + 262144;
constexpr int OFF_GH0   = OFF_Z2    + 262144;   // 512
constexpr int OFF_CFP   = OFF_GH0   + 512;      // 256
constexpr int OFF_ZERO  = OFF_CFP   + 256;      // 512 zeros
constexpr int SCR_TOTAL = OFF_ZERO  + 512;

__device__ float d_scr[SCR_TOTAL];

#define BETTER(v,id,V,I) ((v) > (V) || ((v) == (V) && (id) < (I)))

__device__ __forceinline__ void ins4(float (&tv)[4], int (&ti)[4], float v, int id) {
    if (BETTER(v, id, tv[3], ti[3])) {
        if (BETTER(v, id, tv[0], ti[0])) {
            tv[3]=tv[2]; ti[3]=ti[2]; tv[2]=tv[1]; ti[2]=ti[1];
            tv[1]=tv[0]; ti[1]=ti[0]; tv[0]=v; ti[0]=id;
        } else if (BETTER(v, id, tv[1], ti[1])) {
            tv[3]=tv[2]; ti[3]=ti[2]; tv[2]=tv[1]; ti[2]=ti[1];
            tv[1]=v; ti[1]=id;
        } else if (BETTER(v, id, tv[2], ti[2])) {
            tv[3]=tv[2]; ti[3]=ti[2]; tv[2]=v; ti[2]=id;
        } else {
            tv[3]=v; ti[3]=id;
        }
    }
}

// plain top-4 insert; caller guarantees v > tv[3]. Set-membership only —
// exact order/ties resolved by the fp32 rescore.
__device__ __forceinline__ void ins4p(float (&tv)[4], int (&ti)[4], float v, int id) {
    if (v > tv[1]) {
        tv[3] = tv[2]; ti[3] = ti[2];
        tv[2] = tv[1]; ti[2] = ti[1];
        if (v > tv[0]) { tv[1] = tv[0]; ti[1] = ti[0]; tv[0] = v; ti[0] = id; }
        else           { tv[1] = v; ti[1] = id; }
    } else {
        if (v > tv[2]) { tv[3] = tv[2]; ti[3] = ti[2]; tv[2] = v; ti[2] = id; }
        else           { tv[3] = v; ti[3] = id; }
    }
}

__device__ __forceinline__ uint32_t smem_u32(const void* p) {
    uint32_t a;
    asm("{ .reg .u64 t; cvta.to.shared.u64 t, %1; cvt.u32.u64 %0, t; }" : "=r"(a) : "l"(p));
    return a;
}
#define SW128(o) ((o) ^ (((o) >> 3) & 0x70))

// ======================= prep kernels =======================
__global__ void prepA_kernel(const float* __restrict__ mem,
                             const float* __restrict__ Wk,
                             const float* __restrict__ Wo,
                             float* __restrict__ Apart)
{
    int h = blockIdx.x;
    __shared__ float WoT[64 * 65];
    __shared__ float Mh[64 * 64];
    int t = threadIdx.x;
    #pragma unroll
    for (int p = 0; p < 16; p++) {
        int e = t + p * 256;
        int r = e >> 6, c = e & 63;
        WoT[c * 65 + r] = Wo[e];
    }
    __syncthreads();
    #pragma unroll
    for (int p = 0; p < 16; p++) {
        int e = t + p * 256;
        int dp = e >> 6, j = e & 63;
        const float* mrow = mem + h * 4096 + dp * 64;
        float s = 0.f;
        #pragma unroll
        for (int ee = 0; ee < 64; ee++) s += mrow[ee] * WoT[ee * 65 + j];
        Mh[dp * 64 + j] = s;
    }
    __syncthreads();
    #pragma unroll
    for (int p = 0; p < 16; p++) {
        int e = t + p * 256;
        int i = e >> 6, j = e & 63;
        float s = 0.f;
        #pragma unroll
        for (int dp = 0; dp < 64; dp++)
            s += Wk[(h * 64 + dp) * 64 + i] * Mh[dp * 64 + j];
        Apart[h * 4096 + e] = s;
    }
}

__global__ void reduceAT_kernel(const float* __restrict__ Apart,
                                float* __restrict__ AT)
{
    int e = blockIdx.x * 256 + threadIdx.x;
    int i = e >> 6, j = e & 63;
    float s = 0.f;
    #pragma unroll
    for (int h = 0; h < HH8; h++) s += Apart[h * 4096 + e];
    AT[j * 64 + i] = s * 0.125f;     // AT[j][i] = mean_h A[i][j]
}

// normalize cache keys; emit fp32 (rescore) + bf16 (tensor-core) copies
__global__ void normalize_rows_kernel(const float* __restrict__ src,
                                      float* __restrict__ dst,
                                      __nv_bfloat16* __restrict__ dsth)
{
    int row  = blockIdx.x * 8 + (threadIdx.x >> 5);
    int lane = threadIdx.x & 31;
    float a = src[row * 64 + lane];
    float b = src[row * 64 + 32 + lane];
    float ss = a * a + b * b;
    #pragma unroll
    for (int off = 16; off > 0; off >>= 1)
        ss += __shfl_xor_sync(0xffffffffu, ss, off);
    float inv = 1.0f / fmaxf(sqrtf(ss), 1e-8f);
    float na = a * inv, nb = b * inv;
    dst[row * 64 + lane]       = na;
    dst[row * 64 + 32 + lane]  = nb;
    dsth[row * 64 + lane]      = __float2bfloat16(na);
    dsth[row * 64 + 32 + lane] = __float2bfloat16(nb);
}

__global__ void gh0_kernel(const float* __restrict__ h0, const float* __restrict__ Whh,
                           const float* __restrict__ bhh, float* __restrict__ gh0)
{
    int w = blockIdx.x * 8 + (threadIdx.x >> 5);
    int lane = threadIdx.x & 31;
    const float* row = Whh + w * 128;
    float s = row[lane] * h0[lane] + row[lane + 32] * h0[lane + 32]
            + row[lane + 64] * h0[lane + 64] + row[lane + 96] * h0[lane + 96];
    #pragma unroll
    for (int off = 16; off > 0; off >>= 1)
        s += __shfl_xor_sync(0xffffffffu, s, off);
    if (lane == 0) gh0[w] = s + bhh[w];
}

__global__ void gates0_kernel(const float* __restrict__ gi, const float* __restrict__ gh0,
                              const float* __restrict__ h0, float* __restrict__ h2)
{
    int i = blockIdx.x * 256 + threadIdx.x;
    int b = i >> 7, j = i & 127;
    const float* gib = gi + b * 384;
    float r = 1.0f / (1.0f + expf(-(gib[j] + gh0[j])));
    float u = 1.0f / (1.0f + expf(-(gib[128 + j] + gh0[128 + j])));
    float n = tanhf(gib[256 + j] + r * gh0[256 + j]);
    float h = h0[j];
    h2[i] = (1.0f - u) * n + u * h;
}

__global__ void gates_kernel(const float* __restrict__ gi, const float* __restrict__ gh,
                             const float* __restrict__ hprev, float* __restrict__ h2)
{
    int i = blockIdx.x * 256 + threadIdx.x;
    int b = i >> 7, j = i & 127;
    const float* gib = gi + b * 384;
    const float* ghb = gh + b * 384;
    float r = 1.0f / (1.0f + expf(-(gib[j] + ghb[j])));
    float u = 1.0f / (1.0f + expf(-(gib[128 + j] + ghb[128 + j])));
    float n = tanhf(gib[256 + j] + r * ghb[256 + j]);
    float h = hprev[i];
    h2[i] = (1.0f - u) * n + u * h;
}

// ---- tiled GEMM: C = act((A?P) @ W^T + bias); optional bf16 mirror ----
__global__ __launch_bounds__(256) void gemm_kernel(
    const float* __restrict__ A, const float* __restrict__ P,
    const float* __restrict__ W, const float* __restrict__ bias,
    float* __restrict__ Cm, int N, int K, int act,
    __nv_bfloat16* __restrict__ Ch)
{
    __shared__ float As[16 * 68];
    __shared__ float Ws[16 * 68];
    int tid = threadIdx.x;
    int tx = tid & 15, ty = tid >> 4;
    int m0 = blockIdx.x * 64, n0 = blockIdx.y * 64;
    float acc[16];
    #pragma unroll
    for (int q = 0; q < 16; q++) acc[q] = 0.f;
    int li = tid >> 2;
    int lj = (tid & 3) * 4;
    for (int kt = 0; kt < K; kt += 16) {
        float4 av = *(const float4*)(A + (size_t)(m0 + li) * K + kt + lj);
        if (P) {
            float4 pv = *(const float4*)(P + (size_t)(m0 + li) * K + kt + lj);
            av.x *= pv.x; av.y *= pv.y; av.z *= pv.z; av.w *= pv.w;
        }
        float4 wv = *(const float4*)(W + (size_t)(n0 + li) * K + kt + lj);
        As[(lj + 0) * 68 + li] = av.x; As[(lj + 1) * 68 + li] = av.y;
        As[(lj + 2) * 68 + li] = av.z; As[(lj + 3) * 68 + li] = av.w;
        Ws[(lj + 0) * 68 + li] = wv.x; Ws[(lj + 1) * 68 + li] = wv.y;
        Ws[(lj + 2) * 68 + li] = wv.z; Ws[(lj + 3) * 68 + li] = wv.w;
        __syncthreads();
        #pragma unroll
        for (int k = 0; k < 16; k++) {
            float4 a = *(const float4*)(As + k * 68 + ty * 4);
            float4 b = *(const float4*)(Ws + k * 68 + tx * 4);
            acc[0]+=a.x*b.x; acc[1]+=a.x*b.y; acc[2]+=a.x*b.z; acc[3]+=a.x*b.w;
            acc[4]+=a.y*b.x; acc[5]+=a.y*b.y; acc[6]+=a.y*b.z; acc[7]+=a.y*b.w;
            acc[8]+=a.z*b.x; acc[9]+=a.z*b.y; acc[10]+=a.z*b.z; acc[11]+=a.z*b.w;
            acc[12]+=a.w*b.x; acc[13]+=a.w*b.y; acc[14]+=a.w*b.z; acc[15]+=a.w*b.w;
        }
        __syncthreads();
    }
    float4 bs = *(const float4*)(bias + n0 + tx * 4);
    float bcol[4] = {bs.x, bs.y, bs.z, bs.w};
    #pragma unroll
    for (int rr = 0; rr < 4; rr++) {
        int m = m0 + ty * 4 + rr;
        float4 o;
        float* op = (float*)&o;
        #pragma unroll
        for (int cc = 0; cc < 4; cc++) {
            float v = acc[rr * 4 + cc] + bcol[cc];
            if (act == 1) v = 0.5f * v * (1.0f + erff(v * 0.70710678118654752f));
            op[cc] = v;
        }
        *(float4*)(Cm + (size_t)m * N + n0 + tx * 4) = o;
        if (Ch) {
            #pragma unroll
            for (int cc = 0; cc < 4; cc++)
                Ch[(size_t)m * N + n0 + tx * 4 + cc] = __float2bfloat16(op[cc]);
        }
    }
}

// ---- GI GEMM with gathered A = [zprev | aemb[actions[:,t]]] (K=128) ----
__global__ __launch_bounds__(256) void gi_gemm_kernel(
    const float* __restrict__ zprev, const float* __restrict__ aemb,
    const int* __restrict__ actions, int t,
    const float* __restrict__ W, const float* __restrict__ bias,
    float* __restrict__ Cm, int N)
{
    __shared__ float As[16 * 68];
    __shared__ float Ws[16 * 68];
    __shared__ int aidx[64];
    int tid = threadIdx.x;
    int tx = tid & 15, ty = tid >> 4;
    int m0 = blockIdx.x * 64, n0 = blockIdx.y * 64;
    if (tid < 64) aidx[tid] = actions[(m0 + tid) * 2 + t];
    float acc[16];
    #pragma unroll
    for (int q = 0; q < 16; q++) acc[q] = 0.f;
    int li = tid >> 2;
    int lj = (tid & 3) * 4;
    __syncthreads();
    for (int kt = 0; kt < 128; kt += 16) {
        float4 av;
        if (kt < 64) av = *(const float4*)(zprev + (size_t)(m0 + li) * 64 + kt + lj);
        else         av = *(const float4*)(aemb + (size_t)aidx[li] * 64 + (kt - 64) + lj);
        float4 wv = *(const float4*)(W + (size_t)(n0 + li) * 128 + kt + lj);
        As[(lj + 0) * 68 + li] = av.x; As[(lj + 1) * 68 + li] = av.y;
        As[(lj + 2) * 68 + li] = av.z; As[(lj + 3) * 68 + li] = av.w;
        Ws[(lj + 0) * 68 + li] = wv.x; Ws[(lj + 1) * 68 + li] = wv.y;
        Ws[(lj + 2) * 68 + li] = wv.z; Ws[(lj + 3) * 68 + li] = wv.w;
        __syncthreads();
        #pragma unroll
        for (int k = 0; k < 16; k++) {
            float4 a = *(const float4*)(As + k * 68 + ty * 4);
            float4 b = *(const float4*)(Ws + k * 68 + tx * 4);
            acc[0]+=a.x*b.x; acc[1]+=a.x*b.y; acc[2]+=a.x*b.z; acc[3]+=a.x*b.w;
            acc[4]+=a.y*b.x; acc[5]+=a.y*b.y; acc[6]+=a.y*b.z; acc[7]+=a.y*b.w;
            acc[8]+=a.z*b.x; acc[9]+=a.z*b.y; acc[10]+=a.z*b.z; acc[11]+=a.z*b.w;
            acc[12]+=a.w*b.x; acc[13]+=a.w*b.y; acc[14]+=a.w*b.z; acc[15]+=a.w*b.w;
        }
        __syncthreads();
    }
    float4 bs = *(const float4*)(bias + n0 + tx * 4);
    float bcol[4] = {bs.x, bs.y, bs.z, bs.w};
    #pragma unroll
    for (int rr = 0; rr < 4; rr++) {
        int m = m0 + ty * 4 + rr;
        float4 o;
        float* op = (float*)&o;
        #pragma unroll
        for (int cc = 0; cc < 4; cc++) op[cc] = acc[rr * 4 + cc] + bcol[cc];
        *(float4*)(Cm + (size_t)m * N + n0 + tx * 4) = o;
    }
}

// ---- fused fusion+select ----
__global__ __launch_bounds__(256) void fuse2_kernel(
    const float* __restrict__ z, const float* __restrict__ vc,
    const float* __restrict__ Wf, const float* __restrict__ bf,
    const float* __restrict__ gap, float* __restrict__ out)
{
    __shared__ float As[16 * 68];
    __shared__ float Ws[16 * 68];
    int tid = threadIdx.x;
    int tx = tid & 15, ty = tid >> 4;
    int m0 = blockIdx.x * 64;
    float acc[16];
    #pragma unroll
    for (int q = 0; q < 16; q++) acc[q] = 0.f;
    int li = tid >> 2;
    int lj = (tid & 3) * 4;
    for (int kt = 0; kt < 128; kt += 16) {
        const float* src = (kt < 64) ? (z + (size_t)(m0 + li) * 64 + kt + lj)
                                     : (vc + (size_t)(m0 + li) * 64 + (kt - 64) + lj);
        float4 av = *(const float4*)src;
        float4 wv = *(const float4*)(Wf + (size_t)li * 128 + kt + lj);
        As[(lj + 0) * 68 + li] = av.x; As[(lj + 1) * 68 + li] = av.y;
        As[(lj + 2) * 68 + li] = av.z; As[(lj + 3) * 68 + li] = av.w;
        Ws[(lj + 0) * 68 + li] = wv.x; Ws[(lj + 1) * 68 + li] = wv.y;
        Ws[(lj + 2) * 68 + li] = wv.z; Ws[(lj + 3) * 68 + li] = wv.w;
        __syncthreads();
        #pragma unroll
        for (int k = 0; k < 16; k++) {
            float4 a = *(const float4*)(As + k * 68 + ty * 4);
            float4 b = *(const float4*)(Ws + k * 68 + tx * 4);
            acc[0]+=a.x*b.x; acc[1]+=a.x*b.y; acc[2]+=a.x*b.z; acc[3]+=a.x*b.w;
            acc[4]+=a.y*b.x; acc[5]+=a.y*b.y; acc[6]+=a.y*b.z; acc[7]+=a.y*b.w;
            acc[8]+=a.z*b.x; acc[9]+=a.z*b.y; acc[10]+=a.z*b.z; acc[11]+=a.z*b.w;
            acc[12]+=a.w*b.x; acc[13]+=a.w*b.y; acc[14]+=a.w*b.z; acc[15]+=a.w*b.w;
        }
        __syncthreads();
    }
    float4 bs = *(const float4*)(bf + tx * 4);
    float bcol[4] = {bs.x, bs.y, bs.z, bs.w};
    #pragma unroll
    for (int rr = 0; rr < 4; rr++) {
        int m = m0 + ty * 4 + rr;
        bool act = gap[m] > TAU;
        float4 o;
        float* op = (float*)&o;
        #pragma unroll
        for (int cc = 0; cc < 4; cc++) {
            float v = acc[rr * 4 + cc] + bcol[cc];
            op[cc] = act ? v : z[(size_t)m * 64 + tx * 4 + cc];
        }
        *(float4*)(out + (size_t)m * 64 + tx * 4) = o;
    }
}

// =============== HMMA sims screen v2: hoisted addressing + top-4 + dbuf ===============
// grid (64 m-tiles, 8 splits), 256 threads = 8 warps.
// Warp w: rows msub=(w&3)*16, key-half nhalf=w>>2 (1024 keys, 64/iter).
// All SMEM addresses are loop-invariant (SW128 xor term is per-thread const):
//   SW128(row*128 + k16*16) = row*128 + (k16*16 ^ ((row&7)<<4))
__global__ __launch_bounds__(256) void mma_sims_kernel(
    const __nv_bfloat16* __restrict__ Qh,
    const __nv_bfloat16* __restrict__ KNh,
    int* __restrict__ pidx)
{
    __shared__ __align__(1024) char sm[8192 + 2 * 16384];
    const uint32_t QOFF = 0, KOFF = 8192;
    uint32_t smb = smem_u32(sm);
    int tid = threadIdx.x;
    int warp = tid >> 5, lane = tid & 31;
    int msub = (warp & 3) * 16;
    int nhalf = warp >> 2;
    int m0 = blockIdx.x * 64;
    int c0 = blockIdx.y * 2048;

    // Q tile: 64 rows x 64 bf16 (128B rows, SW128), once
    #pragma unroll
    for (int p = 0; p < 2; p++) {
        int c = tid + p * 256;
        int row = c >> 3, kc = c & 7;
        uint4 v = *(const uint4*)(Qh + (size_t)(m0 + row) * 64 + kc * 8);
        *(uint4*)(sm + QOFF + SW128((uint32_t)(row * 128 + kc * 16))) = v;
    }

    // K-fill: hoisted dst offsets + src pointers (advance by const stride)
    uint32_t kdst[4];
    const uint4* ksrc[4];
    #pragma unroll
    for (int p = 0; p < 4; p++) {
        int c = tid + p * 256;
        int row = c >> 3, kc = c & 7;
        kdst[p] = KOFF + SW128((uint32_t)(row * 128 + kc * 16));
        ksrc[p] = (const uint4*)(KNh + (size_t)(c0 + row) * 64 + kc * 8);
    }

    // A ldmatrix addresses (4, fully hoisted)
    uint32_t aaddr[4];
    {
        int arow = msub + (lane & 15);
        uint32_t xorv = (uint32_t)((arow & 7) << 4);
        #pragma unroll
        for (int kk = 0; kk < 4; kk++)
            aaddr[kk] = smb + QOFF + (uint32_t)(arow * 128)
                      + (((uint32_t)(kk * 32 + (lane >> 4) * 16)) ^ xorv);
    }
    // B ldmatrix: bbase[j2] + bkoff[kk] + bufofs
    uint32_t bbase[4], bkoff[4];
    {
        uint32_t xorv = (uint32_t)((lane & 7) << 4);
        int bsel = (lane >> 3) & 1;
        #pragma unroll
        for (int j2 = 0; j2 < 4; j2++) {
            int keyrow = nhalf * 64 + j2 * 16 + ((lane >> 4) * 8) + (lane & 7);
            bbase[j2] = smb + KOFF + (uint32_t)(keyrow * 128);
        }
        #pragma unroll
        for (int kk = 0; kk < 4; kk++)
            bkoff[kk] = ((uint32_t)(kk * 32 + bsel * 16)) ^ xorv;
    }

    float tv[2][4]; int ti[2][4];
    #pragma unroll
    for (int r = 0; r < 2; r++)
        #pragma unroll
        for (int s = 0; s < 4; s++) { tv[r][s] = NEG; ti[r][s] = 0x7FFFFFFF; }

    // prologue: fill buffer 0 (iter 0)
    #pragma unroll
    for (int p = 0; p < 4; p++) {
        *(uint4*)(sm + kdst[p]) = ksrc[p][0];
        ksrc[p] += 1024;                       // 128 rows * 128B = 16 KB
    }
    __syncthreads();

    for (int it = 0; it < 16; it++) {
        uint32_t bufofs = (uint32_t)(it & 1) * 16384u;
        // prefetch next chunk into the other buffer
        if (it < 15) {
            #pragma unroll
            for (int p = 0; p < 4; p++) {
                *(uint4*)(sm + kdst[p] + (bufofs ^ 16384u)) = ksrc[p][0];
                ksrc[p] += 1024;
            }
        }

        float acc[8][4];
        #pragma unroll
        for (int j = 0; j < 8; j++)
            #pragma unroll
            for (int q = 0; q < 4; q++) acc[j][q] = 0.f;

        #pragma unroll
        for (int kk = 0; kk < 4; kk++) {
            uint32_t a0, a1, a2, a3;
            asm volatile("ldmatrix.sync.aligned.m8n8.x4.shared.b16 {%0,%1,%2,%3}, [%4];"
                         : "=r"(a0), "=r"(a1), "=r"(a2), "=r"(a3) : "r"(aaddr[kk]));
            #pragma unroll
            for (int j2 = 0; j2 < 4; j2++) {
                uint32_t baddr = bbase[j2] + bkoff[kk] + bufofs;
                uint32_t b0, b1, b2, b3;
                asm volatile("ldmatrix.sync.aligned.m8n8.x4.shared.b16 {%0,%1,%2,%3}, [%4];"
                             : "=r"(b0), "=r"(b1), "=r"(b2), "=r"(b3) : "r"(baddr));
                int j = j2 * 2;
                asm volatile("mma.sync.aligned.m16n8k16.row.col.f32.bf16.bf16.f32 "
                             "{%0,%1,%2,%3}, {%4,%5,%6,%7}, {%8,%9}, {%0,%1,%2,%3};"
                             : "+f"(acc[j][0]), "+f"(acc[j][1]), "+f"(acc[j][2]), "+f"(acc[j][3])
                             : "r"(a0), "r"(a1), "r"(a2), "r"(a3), "r"(b0), "r"(b1));
                asm volatile("mma.sync.aligned.m16n8k16.row.col.f32.bf16.bf16.f32 "
                             "{%0,%1,%2,%3}, {%4,%5,%6,%7}, {%8,%9}, {%0,%1,%2,%3};"
                             : "+f"(acc[j+1][0]), "+f"(acc[j+1][1]), "+f"(acc[j+1][2]), "+f"(acc[j+1][3])
                             : "r"(a0), "r"(a1), "r"(a2), "r"(a3), "r"(b2), "r"(b3));
            }
        }

        // extraction: D rows (msub+g, +8), cols (lane&3)*2 (+1) within 8-key group j
        int idb0 = c0 + it * 128 + nhalf * 64 + (lane & 3) * 2;
        #pragma unroll
        for (int j = 0; j < 8; j++) {
            int idb = idb0 + j * 8;
            if (acc[j][0] > tv[0][3]) ins4p(tv[0], ti[0], acc[j][0], idb);
            if (acc[j][1] > tv[0][3]) ins4p(tv[0], ti[0], acc[j][1], idb + 1);
            if (acc[j][2] > tv[1][3]) ins4p(tv[1], ti[1], acc[j][2], idb);
            if (acc[j][3] > tv[1][3]) ins4p(tv[1], ti[1], acc[j][3], idb + 1);
        }
        __syncthreads();
    }

    // merge the 4 lanes (tig) sharing each row -> top-4 per (row, half)
    #pragma unroll
    for (int step = 1; step <= 2; step <<= 1) {
        #pragma unroll
        for (int r = 0; r < 2; r++) {
            float ov[4]; int oi[4];
            #pragma unroll
            for (int s = 0; s < 4; s++) {
                ov[s] = __shfl_xor_sync(0xffffffffu, tv[r][s], step);
                oi[s] = __shfl_xor_sync(0xffffffffu, ti[r][s], step);
            }
            #pragma unroll
            for (int s = 0; s < 4; s++)
                if (ov[s] > tv[r][3]) ins4p(tv[r], ti[r], ov[s], oi[s]);
        }
    }

    if ((lane & 3) == 0) {
        int g = lane >> 2;
        int row0 = m0 + msub + g;
        int row1 = row0 + 8;
        int base0 = ((row0 * 8 + blockIdx.y) * 2 + nhalf) * 4;
        int base1 = ((row1 * 8 + blockIdx.y) * 2 + nhalf) * 4;
        #pragma unroll
        for (int s = 0; s < 4; s++) {
            pidx[base0 + s] = ti[0][s];
            pidx[base1 + s] = ti[1][s];
        }
    }
}

// ===== rescore 64 candidates/row (fp32) -> top-4 -> gather; vmem inline =====
__global__ void rescore_kernel(const float* __restrict__ Q, const float* __restrict__ KN,
                               const int* __restrict__ pidx, const float* __restrict__ AT,
                               const float* __restrict__ cvals, float* __restrict__ vc)
{
    int b = blockIdx.x;
    int t = threadIdx.x;          // 64 threads
    __shared__ float qrow[64];
    __shared__ float vals[64];
    __shared__ int   ids[64];
    __shared__ int   sidx[4];
    qrow[t] = Q[b * 64 + t];
    __syncthreads();
    int id = pidx[b * 64 + t];
    const float4* kr = (const float4*)(KN + (size_t)id * 64);
    const float4* q4 = (const float4*)qrow;
    float s = 0.f;
    #pragma unroll
    for (int j = 0; j < 16; j++) {
        float4 kv = kr[j];
        float4 qv = q4[j];
        s += qv.x * kv.x + qv.y * kv.y + qv.z * kv.z + qv.w * kv.w;
    }
    vals[t] = s; ids[t] = id;
    __syncthreads();
    if (t == 0) {
        float bv[4] = {NEG, NEG, NEG, NEG};
        int bi[4] = {0x7FFFFFFF, 0x7FFFFFFF, 0x7FFFFFFF, 0x7FFFFFFF};
        for (int j = 0; j < 64; j++) ins4(bv, bi, vals[j], ids[j]);
        sidx[0]=bi[0]; sidx[1]=bi[1]; sidx[2]=bi[2]; sidx[3]=bi[3];
    }
    __syncthreads();
    // vmem[b][t] = sum_i qrow[i] * AT[t*64+i]
    const float4* ar = (const float4*)(AT + (size_t)t * 64);
    float vm = 0.f;
    #pragma unroll
    for (int j = 0; j < 16; j++) {
        float4 av = ar[j];
        float4 qv = q4[j];
        vm += qv.x * av.x + qv.y * av.y + qv.z * av.z + qv.w * av.w;
    }
    float sum = cvals[(size_t)sidx[0] * 64 + t] + cvals[(size_t)sidx[1] * 64 + t]
              + cvals[(size_t)sidx[2] * 64 + t] + cvals[(size_t)sidx[3] * 64 + t];
    vc[b * 64 + t] = 0.5f * (vm + sum * 0.25f);
}

__global__ void cf_partial_kernel(const float* __restrict__ z1, const float* __restrict__ z2,
                                  const float* __restrict__ z, const float* __restrict__ vc,
                                  float* __restrict__ part)
{
    __shared__ float red[256];
    float s = 0.f;
    for (int i = blockIdx.x * 256 + threadIdx.x; i < BB * DD; i += 256 * 256) {
        float d = 0.5f * (z1[i] + z2[i]) - z[i] - vc[i];
        s += d * d;
    }
    red[threadIdx.x] = s;
    __syncthreads();
    for (int st = 128; st > 0; st >>= 1) {
        if (threadIdx.x < st) red[threadIdx.x] += red[threadIdx.x + st];
        __syncthreads();
    }
    if (threadIdx.x == 0) part[blockIdx.x] = red[0];
}

__global__ void cf_final_kernel(const float* __restrict__ part, float* __restrict__ out)
{
    __shared__ float red[256];
    red[threadIdx.x] = part[threadIdx.x];
    __syncthreads();
    for (int st = 128; st > 0; st >>= 1) {
        if (threadIdx.x < st) red[threadIdx.x] += red[threadIdx.x + st];
        __syncthreads();
    }
    if (threadIdx.x == 0) out[BB * DD] = red[0] * (1.0f / (float)(BB * DD));
}

extern "C" void kernel_launch(void* const* d_in, const int* in_sizes, int n_in,
                              void* d_out, int out_size)
{
    const float* z    = (const float*)d_in[0];
    const float* hot  = (const float*)d_in[2];
    const float* gap  = (const float*)d_in[3];
    const float* Wq   = (const float*)d_in[4];
    const float* bq   = (const float*)d_in[5];
    const float* Wf   = (const float*)d_in[6];
    const float* bf   = (const float*)d_in[7];
    const float* mem  = (const float*)d_in[8];
    const float* Wk   = (const float*)d_in[9];
    const float* Wo   = (const float*)d_in[10];
    const float* ck   = (const float*)d_in[11];
    const float* cvals= (const float*)d_in[12];
    const float* aemb = (const float*)d_in[13];
    const float* Wih  = (const float*)d_in[14];
    const float* Whh  = (const float*)d_in[15];
    const float* bih  = (const float*)d_in[16];
    const float* bhh  = (const float*)d_in[17];
    const float* h0   = (const float*)d_in[18];
    const float* Wo1  = (const float*)d_in[19];
    const float* bo1  = (const float*)d_in[20];
    const float* Wo2  = (const float*)d_in[21];
    const float* bo2  = (const float*)d_in[22];
    const int*   acts = (const int*)d_in[23];
    float* out = (float*)d_out;

    float* scr = nullptr;
    cudaGetSymbolAddress((void**)&scr, d_scr);
    __nv_bfloat16* Qh  = (__nv_bfloat16*)(scr + OFF_QH);
    __nv_bfloat16* KNh = (__nv_bfloat16*)(scr + OFF_KNH);

    // ordered so mma_sims is the 4th launch (ncu anchor)
    normalize_rows_kernel<<<2048, 256>>>(ck, scr + OFF_KN, KNh);                       // 1
    gemm_kernel<<<dim3(64, 1), 256>>>(z, hot, Wq, bq, scr + OFF_Q, 64, 64, 0, Qh);     // 2
    prepA_kernel<<<8, 256>>>(mem, Wk, Wo, scr + OFF_APART);                            // 3
    mma_sims_kernel<<<dim3(64, 8), 256>>>(Qh, KNh, (int*)(scr + OFF_PIDX));            // 4
    reduceAT_kernel<<<16, 256>>>(scr + OFF_APART, scr + OFF_AT);                       // 5
    rescore_kernel<<<BB, 64>>>(scr + OFF_Q, scr + OFF_KN, (int*)(scr + OFF_PIDX),
                               scr + OFF_AT, cvals, scr + OFF_VC);                     // 6

    // GRU rollout, T=2; GH(t=0) collapses to a 384-vector
    gh0_kernel<<<48, 256>>>(h0, Whh, bhh, scr + OFF_GH0);
    // t = 0
    gi_gemm_kernel<<<dim3(64, 6), 256>>>(z, aemb, acts, 0, Wih, bih, scr + OFF_GI, 384);
    gates0_kernel<<<2048, 256>>>(scr + OFF_GI, scr + OFF_GH0, h0, scr + OFF_H2A);
    gemm_kernel<<<dim3(64, 2), 256>>>(scr + OFF_H2A, nullptr, Wo1, bo1, scr + OFF_HID, 128, 128, 1, nullptr);
    gemm_kernel<<<dim3(64, 1), 256>>>(scr + OFF_HID, nullptr, Wo2, bo2, scr + OFF_Z1, 64, 128, 0, nullptr);
    // t = 1
    gi_gemm_kernel<<<dim3(64, 6), 256>>>(scr + OFF_Z1, aemb, acts, 1, Wih, bih, scr + OFF_GI, 384);
    gemm_kernel<<<dim3(64, 6), 256>>>(scr + OFF_H2A, nullptr, Whh, bhh, scr + OFF_GH, 384, 128, 0, nullptr);
    gates_kernel<<<2048, 256>>>(scr + OFF_GI, scr + OFF_GH, scr + OFF_H2A, scr + OFF_H2B);
    gemm_kernel<<<dim3(64, 2), 256>>>(scr + OFF_H2B, nullptr, Wo1, bo1, scr + OFF_HID, 128, 128, 1, nullptr);
    gemm_kernel<<<dim3(64, 1), 256>>>(scr + OFF_HID, nullptr, Wo2, bo2, scr + OFF_Z2, 64, 128, 0, nullptr);

    // cf loss
    cf_partial_kernel<<<256, 256>>>(scr + OFF_Z1, scr + OFF_Z2, z, scr + OFF_VC, scr + OFF_CFP);
    cf_final_kernel<<<1, 256>>>(scr + OFF_CFP, out);

    // fused fusion + masked select
    fuse2_kernel<<<64, 256>>>(z, scr + OFF_VC, Wf, bf, gap, out);
}

// round 10
// speedup vs baseline: 3.3846x; 1.2823x over previous
#include <cuda_runtime.h>
#include <cuda_bf16.h>
#include <cstdint>

#define BB 4096
#define DD 64
#define HH8 8
#define CC 16384
#define TAU 0.3f
#define NEG (-1e30f)

// ---- scratch offsets (floats) ----
constexpr int OFF_AT    = 0;
constexpr int OFF_APART = OFF_AT    + 4096;
constexpr int OFF_KN    = OFF_APART + 32768;
constexpr int OFF_Q     = OFF_KN    + 1048576;
constexpr int OFF_VC    = OFF_Q     + 262144;
constexpr int OFF_PIDX  = OFF_VC    + 262144;   // 4096*8*2*4 ints
constexpr int OFF_QH    = OFF_PIDX  + 262144;   // 4096*64 bf16
constexpr int OFF_KNH   = OFF_QH    + 131072;   // 16384*64 bf16
constexpr int OFF_GI    = OFF_KNH   + 524288;
constexpr int OFF_GH    = OFF_GI    + 1572864;
constexpr int OFF_H2A   = OFF_GH    + 1572864;
constexpr int OFF_H2B   = OFF_H2A   + 524288;
constexpr int OFF_HID   = OFF_H2B   + 524288;
constexpr int OFF_Z1    = OFF_HID   + 524288;
constexpr int OFF_Z2    = OFF_Z1    + 262144;
constexpr int OFF_GH0   = OFF_Z2    + 262144;   // 512
constexpr int OFF_CFP   = OFF_GH0   + 512;      // 256
constexpr int OFF_ZERO  = OFF_CFP   + 256;      // 512 zeros
constexpr int SCR_TOTAL = OFF_ZERO  + 512;

__device__ float d_scr[SCR_TOTAL];

#define BETTER(v,id,V,I) ((v) > (V) || ((v) == (V) && (id) < (I)))

__device__ __forceinline__ void ins4(float (&tv)[4], int (&ti)[4], float v, int id) {
    if (BETTER(v, id, tv[3], ti[3])) {
        if (BETTER(v, id, tv[0], ti[0])) {
            tv[3]=tv[2]; ti[3]=ti[2]; tv[2]=tv[1]; ti[2]=ti[1];
            tv[1]=tv[0]; ti[1]=ti[0]; tv[0]=v; ti[0]=id;
        } else if (BETTER(v, id, tv[1], ti[1])) {
            tv[3]=tv[2]; ti[3]=ti[2]; tv[2]=tv[1]; ti[2]=ti[1];
            tv[1]=v; ti[1]=id;
        } else if (BETTER(v, id, tv[2], ti[2])) {
            tv[3]=tv[2]; ti[3]=ti[2]; tv[2]=v; ti[2]=id;
        } else {
            tv[3]=v; ti[3]=id;
        }
    }
}

// plain top-4 insert; caller guarantees v > tv[3]. Set-membership only —
// exact order/ties resolved by the fp32 rescore.
__device__ __forceinline__ void ins4p(float (&tv)[4], int (&ti)[4], float v, int id) {
    if (v > tv[1]) {
        tv[3] = tv[2]; ti[3] = ti[2];
        tv[2] = tv[1]; ti[2] = ti[1];
        if (v > tv[0]) { tv[1] = tv[0]; ti[1] = ti[0]; tv[0] = v; ti[0] = id; }
        else           { tv[1] = v; ti[1] = id; }
    } else {
        if (v > tv[2]) { tv[3] = tv[2]; ti[3] = ti[2]; tv[2] = v; ti[2] = id; }
        else           { tv[3] = v; ti[3] = id; }
    }
}

__device__ __forceinline__ uint32_t smem_u32(const void* p) {
    uint32_t a;
    asm("{ .reg .u64 t; cvta.to.shared.u64 t, %1; cvt.u32.u64 %0, t; }" : "=r"(a) : "l"(p));
    return a;
}
#define SW128(o) ((o) ^ (((o) >> 3) & 0x70))

// ======================= prep kernels =======================
__global__ void prepA_kernel(const float* __restrict__ mem,
                             const float* __restrict__ Wk,
                             const float* __restrict__ Wo,
                             float* __restrict__ Apart)
{
    int h = blockIdx.x;
    __shared__ float WoT[64 * 65];
    __shared__ float Mh[64 * 64];
    int t = threadIdx.x;
    #pragma unroll
    for (int p = 0; p < 16; p++) {
        int e = t + p * 256;
        int r = e >> 6, c = e & 63;
        WoT[c * 65 + r] = Wo[e];
    }
    __syncthreads();
    #pragma unroll
    for (int p = 0; p < 16; p++) {
        int e = t + p * 256;
        int dp = e >> 6, j = e & 63;
        const float* mrow = mem + h * 4096 + dp * 64;
        float s = 0.f;
        #pragma unroll
        for (int ee = 0; ee < 64; ee++) s += mrow[ee] * WoT[ee * 65 + j];
        Mh[dp * 64 + j] = s;
    }
    __syncthreads();
    #pragma unroll
    for (int p = 0; p < 16; p++) {
        int e = t + p * 256;
        int i = e >> 6, j = e & 63;
        float s = 0.f;
        #pragma unroll
        for (int dp = 0; dp < 64; dp++)
            s += Wk[(h * 64 + dp) * 64 + i] * Mh[dp * 64 + j];
        Apart[h * 4096 + e] = s;
    }
}

__global__ void reduceAT_kernel(const float* __restrict__ Apart,
                                float* __restrict__ AT)
{
    int e = blockIdx.x * 256 + threadIdx.x;
    int i = e >> 6, j = e & 63;
    float s = 0.f;
    #pragma unroll
    for (int h = 0; h < HH8; h++) s += Apart[h * 4096 + e];
    AT[j * 64 + i] = s * 0.125f;
}

// normalize cache keys; emit fp32 (rescore) + bf16 (tensor-core) copies
__global__ void normalize_rows_kernel(const float* __restrict__ src,
                                      float* __restrict__ dst,
                                      __nv_bfloat16* __restrict__ dsth)
{
    int row  = blockIdx.x * 8 + (threadIdx.x >> 5);
    int lane = threadIdx.x & 31;
    float a = src[row * 64 + lane];
    float b = src[row * 64 + 32 + lane];
    float ss = a * a + b * b;
    #pragma unroll
    for (int off = 16; off > 0; off >>= 1)
        ss += __shfl_xor_sync(0xffffffffu, ss, off);
    float inv = 1.0f / fmaxf(sqrtf(ss), 1e-8f);
    float na = a * inv, nb = b * inv;
    dst[row * 64 + lane]       = na;
    dst[row * 64 + 32 + lane]  = nb;
    dsth[row * 64 + lane]      = __float2bfloat16(na);
    dsth[row * 64 + 32 + lane] = __float2bfloat16(nb);
}

__global__ void gh0_kernel(const float* __restrict__ h0, const float* __restrict__ Whh,
                           const float* __restrict__ bhh, float* __restrict__ gh0)
{
    int w = blockIdx.x * 8 + (threadIdx.x >> 5);
    int lane = threadIdx.x & 31;
    const float* row = Whh + w * 128;
    float s = row[lane] * h0[lane] + row[lane + 32] * h0[lane + 32]
            + row[lane + 64] * h0[lane + 64] + row[lane + 96] * h0[lane + 96];
    #pragma unroll
    for (int off = 16; off > 0; off >>= 1)
        s += __shfl_xor_sync(0xffffffffu, s, off);
    if (lane == 0) gh0[w] = s + bhh[w];
}

__global__ void gates0_kernel(const float* __restrict__ gi, const float* __restrict__ gh0,
                              const float* __restrict__ h0, float* __restrict__ h2)
{
    int i = blockIdx.x * 256 + threadIdx.x;
    int b = i >> 7, j = i & 127;
    const float* gib = gi + b * 384;
    float r = 1.0f / (1.0f + expf(-(gib[j] + gh0[j])));
    float u = 1.0f / (1.0f + expf(-(gib[128 + j] + gh0[128 + j])));
    float n = tanhf(gib[256 + j] + r * gh0[256 + j]);
    float h = h0[j];
    h2[i] = (1.0f - u) * n + u * h;
}

__global__ void gates_kernel(const float* __restrict__ gi, const float* __restrict__ gh,
                             const float* __restrict__ hprev, float* __restrict__ h2)
{
    int i = blockIdx.x * 256 + threadIdx.x;
    int b = i >> 7, j = i & 127;
    const float* gib = gi + b * 384;
    const float* ghb = gh + b * 384;
    float r = 1.0f / (1.0f + expf(-(gib[j] + ghb[j])));
    float u = 1.0f / (1.0f + expf(-(gib[128 + j] + ghb[128 + j])));
    float n = tanhf(gib[256 + j] + r * ghb[256 + j]);
    float h = hprev[i];
    h2[i] = (1.0f - u) * n + u * h;
}

// ---- tiled GEMM: C = act((A?P) @ W^T + bias); optional bf16 mirror ----
__global__ __launch_bounds__(256) void gemm_kernel(
    const float* __restrict__ A, const float* __restrict__ P,
    const float* __restrict__ W, const float* __restrict__ bias,
    float* __restrict__ Cm, int N, int K, int act,
    __nv_bfloat16* __restrict__ Ch)
{
    __shared__ float As[16 * 68];
    __shared__ float Ws[16 * 68];
    int tid = threadIdx.x;
    int tx = tid & 15, ty = tid >> 4;
    int m0 = blockIdx.x * 64, n0 = blockIdx.y * 64;
    float acc[16];
    #pragma unroll
    for (int q = 0; q < 16; q++) acc[q] = 0.f;
    int li = tid >> 2;
    int lj = (tid & 3) * 4;
    for (int kt = 0; kt < K; kt += 16) {
        float4 av = *(const float4*)(A + (size_t)(m0 + li) * K + kt + lj);
        if (P) {
            float4 pv = *(const float4*)(P + (size_t)(m0 + li) * K + kt + lj);
            av.x *= pv.x; av.y *= pv.y; av.z *= pv.z; av.w *= pv.w;
        }
        float4 wv = *(const float4*)(W + (size_t)(n0 + li) * K + kt + lj);
        As[(lj + 0) * 68 + li] = av.x; As[(lj + 1) * 68 + li] = av.y;
        As[(lj + 2) * 68 + li] = av.z; As[(lj + 3) * 68 + li] = av.w;
        Ws[(lj + 0) * 68 + li] = wv.x; Ws[(lj + 1) * 68 + li] = wv.y;
        Ws[(lj + 2) * 68 + li] = wv.z; Ws[(lj + 3) * 68 + li] = wv.w;
        __syncthreads();
        #pragma unroll
        for (int k = 0; k < 16; k++) {
            float4 a = *(const float4*)(As + k * 68 + ty * 4);
            float4 b = *(const float4*)(Ws + k * 68 + tx * 4);
            acc[0]+=a.x*b.x; acc[1]+=a.x*b.y; acc[2]+=a.x*b.z; acc[3]+=a.x*b.w;
            acc[4]+=a.y*b.x; acc[5]+=a.y*b.y; acc[6]+=a.y*b.z; acc[7]+=a.y*b.w;
            acc[8]+=a.z*b.x; acc[9]+=a.z*b.y; acc[10]+=a.z*b.z; acc[11]+=a.z*b.w;
            acc[12]+=a.w*b.x; acc[13]+=a.w*b.y; acc[14]+=a.w*b.z; acc[15]+=a.w*b.w;
        }
        __syncthreads();
    }
    float4 bs = *(const float4*)(bias + n0 + tx * 4);
    float bcol[4] = {bs.x, bs.y, bs.z, bs.w};
    #pragma unroll
    for (int rr = 0; rr < 4; rr++) {
        int m = m0 + ty * 4 + rr;
        float4 o;
        float* op = (float*)&o;
        #pragma unroll
        for (int cc = 0; cc < 4; cc++) {
            float v = acc[rr * 4 + cc] + bcol[cc];
            if (act == 1) v = 0.5f * v * (1.0f + erff(v * 0.70710678118654752f));
            op[cc] = v;
        }
        *(float4*)(Cm + (size_t)m * N + n0 + tx * 4) = o;
        if (Ch) {
            #pragma unroll
            for (int cc = 0; cc < 4; cc++)
                Ch[(size_t)m * N + n0 + tx * 4 + cc] = __float2bfloat16(op[cc]);
        }
    }
}

// ---- GI GEMM with gathered A = [zprev | aemb[actions[:,t]]] (K=128) ----
__global__ __launch_bounds__(256) void gi_gemm_kernel(
    const float* __restrict__ zprev, const float* __restrict__ aemb,
    const int* __restrict__ actions, int t,
    const float* __restrict__ W, const float* __restrict__ bias,
    float* __restrict__ Cm, int N)
{
    __shared__ float As[16 * 68];
    __shared__ float Ws[16 * 68];
    __shared__ int aidx[64];
    int tid = threadIdx.x;
    int tx = tid & 15, ty = tid >> 4;
    int m0 = blockIdx.x * 64, n0 = blockIdx.y * 64;
    if (tid < 64) aidx[tid] = actions[(m0 + tid) * 2 + t];
    float acc[16];
    #pragma unroll
    for (int q = 0; q < 16; q++) acc[q] = 0.f;
    int li = tid >> 2;
    int lj = (tid & 3) * 4;
    __syncthreads();
    for (int kt = 0; kt < 128; kt += 16) {
        float4 av;
        if (kt < 64) av = *(const float4*)(zprev + (size_t)(m0 + li) * 64 + kt + lj);
        else         av = *(const float4*)(aemb + (size_t)aidx[li] * 64 + (kt - 64) + lj);
        float4 wv = *(const float4*)(W + (size_t)(n0 + li) * 128 + kt + lj);
        As[(lj + 0) * 68 + li] = av.x; As[(lj + 1) * 68 + li] = av.y;
        As[(lj + 2) * 68 + li] = av.z; As[(lj + 3) * 68 + li] = av.w;
        Ws[(lj + 0) * 68 + li] = wv.x; Ws[(lj + 1) * 68 + li] = wv.y;
        Ws[(lj + 2) * 68 + li] = wv.z; Ws[(lj + 3) * 68 + li] = wv.w;
        __syncthreads();
        #pragma unroll
        for (int k = 0; k < 16; k++) {
            float4 a = *(const float4*)(As + k * 68 + ty * 4);
            float4 b = *(const float4*)(Ws + k * 68 + tx * 4);
            acc[0]+=a.x*b.x; acc[1]+=a.x*b.y; acc[2]+=a.x*b.z; acc[3]+=a.x*b.w;
            acc[4]+=a.y*b.x; acc[5]+=a.y*b.y; acc[6]+=a.y*b.z; acc[7]+=a.y*b.w;
            acc[8]+=a.z*b.x; acc[9]+=a.z*b.y; acc[10]+=a.z*b.z; acc[11]+=a.z*b.w;
            acc[12]+=a.w*b.x; acc[13]+=a.w*b.y; acc[14]+=a.w*b.z; acc[15]+=a.w*b.w;
        }
        __syncthreads();
    }
    float4 bs = *(const float4*)(bias + n0 + tx * 4);
    float bcol[4] = {bs.x, bs.y, bs.z, bs.w};
    #pragma unroll
    for (int rr = 0; rr < 4; rr++) {
        int m = m0 + ty * 4 + rr;
        float4 o;
        float* op = (float*)&o;
        #pragma unroll
        for (int cc = 0; cc < 4; cc++) op[cc] = acc[rr * 4 + cc] + bcol[cc];
        *(float4*)(Cm + (size_t)m * N + n0 + tx * 4) = o;
    }
}

// ---- fused fusion+select ----
__global__ __launch_bounds__(256) void fuse2_kernel(
    const float* __restrict__ z, const float* __restrict__ vc,
    const float* __restrict__ Wf, const float* __restrict__ bf,
    const float* __restrict__ gap, float* __restrict__ out)
{
    __shared__ float As[16 * 68];
    __shared__ float Ws[16 * 68];
    int tid = threadIdx.x;
    int tx = tid & 15, ty = tid >> 4;
    int m0 = blockIdx.x * 64;
    float acc[16];
    #pragma unroll
    for (int q = 0; q < 16; q++) acc[q] = 0.f;
    int li = tid >> 2;
    int lj = (tid & 3) * 4;
    for (int kt = 0; kt < 128; kt += 16) {
        const float* src = (kt < 64) ? (z + (size_t)(m0 + li) * 64 + kt + lj)
                                     : (vc + (size_t)(m0 + li) * 64 + (kt - 64) + lj);
        float4 av = *(const float4*)src;
        float4 wv = *(const float4*)(Wf + (size_t)li * 128 + kt + lj);
        As[(lj + 0) * 68 + li] = av.x; As[(lj + 1) * 68 + li] = av.y;
        As[(lj + 2) * 68 + li] = av.z; As[(lj + 3) * 68 + li] = av.w;
        Ws[(lj + 0) * 68 + li] = wv.x; Ws[(lj + 1) * 68 + li] = wv.y;
        Ws[(lj + 2) * 68 + li] = wv.z; Ws[(lj + 3) * 68 + li] = wv.w;
        __syncthreads();
        #pragma unroll
        for (int k = 0; k < 16; k++) {
            float4 a = *(const float4*)(As + k * 68 + ty * 4);
            float4 b = *(const float4*)(Ws + k * 68 + tx * 4);
            acc[0]+=a.x*b.x; acc[1]+=a.x*b.y; acc[2]+=a.x*b.z; acc[3]+=a.x*b.w;
            acc[4]+=a.y*b.x; acc[5]+=a.y*b.y; acc[6]+=a.y*b.z; acc[7]+=a.y*b.w;
            acc[8]+=a.z*b.x; acc[9]+=a.z*b.y; acc[10]+=a.z*b.z; acc[11]+=a.z*b.w;
            acc[12]+=a.w*b.x; acc[13]+=a.w*b.y; acc[14]+=a.w*b.z; acc[15]+=a.w*b.w;
        }
        __syncthreads();
    }
    float4 bs = *(const float4*)(bf + tx * 4);
    float bcol[4] = {bs.x, bs.y, bs.z, bs.w};
    #pragma unroll
    for (int rr = 0; rr < 4; rr++) {
        int m = m0 + ty * 4 + rr;
        bool act = gap[m] > TAU;
        float4 o;
        float* op = (float*)&o;
        #pragma unroll
        for (int cc = 0; cc < 4; cc++) {
            float v = acc[rr * 4 + cc] + bcol[cc];
            op[cc] = act ? v : z[(size_t)m * 64 + tx * 4 + cc];
        }
        *(float4*)(out + (size_t)m * 64 + tx * 4) = o;
    }
}

// =============== HMMA sims screen (round-9 version, unchanged) ===============
__global__ __launch_bounds__(256) void mma_sims_kernel(
    const __nv_bfloat16* __restrict__ Qh,
    const __nv_bfloat16* __restrict__ KNh,
    int* __restrict__ pidx)
{
    __shared__ __align__(1024) char sm[8192 + 2 * 16384];
    const uint32_t QOFF = 0, KOFF = 8192;
    uint32_t smb = smem_u32(sm);
    int tid = threadIdx.x;
    int warp = tid >> 5, lane = tid & 31;
    int msub = (warp & 3) * 16;
    int nhalf = warp >> 2;
    int m0 = blockIdx.x * 64;
    int c0 = blockIdx.y * 2048;

    #pragma unroll
    for (int p = 0; p < 2; p++) {
        int c = tid + p * 256;
        int row = c >> 3, kc = c & 7;
        uint4 v = *(const uint4*)(Qh + (size_t)(m0 + row) * 64 + kc * 8);
        *(uint4*)(sm + QOFF + SW128((uint32_t)(row * 128 + kc * 16))) = v;
    }

    uint32_t kdst[4];
    const uint4* ksrc[4];
    #pragma unroll
    for (int p = 0; p < 4; p++) {
        int c = tid + p * 256;
        int row = c >> 3, kc = c & 7;
        kdst[p] = KOFF + SW128((uint32_t)(row * 128 + kc * 16));
        ksrc[p] = (const uint4*)(KNh + (size_t)(c0 + row) * 64 + kc * 8);
    }

    uint32_t aaddr[4];
    {
        int arow = msub + (lane & 15);
        uint32_t xorv = (uint32_t)((arow & 7) << 4);
        #pragma unroll
        for (int kk = 0; kk < 4; kk++)
            aaddr[kk] = smb + QOFF + (uint32_t)(arow * 128)
                      + (((uint32_t)(kk * 32 + (lane >> 4) * 16)) ^ xorv);
    }
    uint32_t bbase[4], bkoff[4];
    {
        uint32_t xorv = (uint32_t)((lane & 7) << 4);
        int bsel = (lane >> 3) & 1;
        #pragma unroll
        for (int j2 = 0; j2 < 4; j2++) {
            int keyrow = nhalf * 64 + j2 * 16 + ((lane >> 4) * 8) + (lane & 7);
            bbase[j2] = smb + KOFF + (uint32_t)(keyrow * 128);
        }
        #pragma unroll
        for (int kk = 0; kk < 4; kk++)
            bkoff[kk] = ((uint32_t)(kk * 32 + bsel * 16)) ^ xorv;
    }

    float tv[2][4]; int ti[2][4];
    #pragma unroll
    for (int r = 0; r < 2; r++)
        #pragma unroll
        for (int s = 0; s < 4; s++) { tv[r][s] = NEG; ti[r][s] = 0x7FFFFFFF; }

    #pragma unroll
    for (int p = 0; p < 4; p++) {
        *(uint4*)(sm + kdst[p]) = ksrc[p][0];
        ksrc[p] += 1024;
    }
    __syncthreads();

    for (int it = 0; it < 16; it++) {
        uint32_t bufofs = (uint32_t)(it & 1) * 16384u;
        if (it < 15) {
            #pragma unroll
            for (int p = 0; p < 4; p++) {
                *(uint4*)(sm + kdst[p] + (bufofs ^ 16384u)) = ksrc[p][0];
                ksrc[p] += 1024;
            }
        }

        float acc[8][4];
        #pragma unroll
        for (int j = 0; j < 8; j++)
            #pragma unroll
            for (int q = 0; q < 4; q++) acc[j][q] = 0.f;

        #pragma unroll
        for (int kk = 0; kk < 4; kk++) {
            uint32_t a0, a1, a2, a3;
            asm volatile("ldmatrix.sync.aligned.m8n8.x4.shared.b16 {%0,%1,%2,%3}, [%4];"
                         : "=r"(a0), "=r"(a1), "=r"(a2), "=r"(a3) : "r"(aaddr[kk]));
            #pragma unroll
            for (int j2 = 0; j2 < 4; j2++) {
                uint32_t baddr = bbase[j2] + bkoff[kk] + bufofs;
                uint32_t b0, b1, b2, b3;
                asm volatile("ldmatrix.sync.aligned.m8n8.x4.shared.b16 {%0,%1,%2,%3}, [%4];"
                             : "=r"(b0), "=r"(b1), "=r"(b2), "=r"(b3) : "r"(baddr));
                int j = j2 * 2;
                asm volatile("mma.sync.aligned.m16n8k16.row.col.f32.bf16.bf16.f32 "
                             "{%0,%1,%2,%3}, {%4,%5,%6,%7}, {%8,%9}, {%0,%1,%2,%3};"
                             : "+f"(acc[j][0]), "+f"(acc[j][1]), "+f"(acc[j][2]), "+f"(acc[j][3])
                             : "r"(a0), "r"(a1), "r"(a2), "r"(a3), "r"(b0), "r"(b1));
                asm volatile("mma.sync.aligned.m16n8k16.row.col.f32.bf16.bf16.f32 "
                             "{%0,%1,%2,%3}, {%4,%5,%6,%7}, {%8,%9}, {%0,%1,%2,%3};"
                             : "+f"(acc[j+1][0]), "+f"(acc[j+1][1]), "+f"(acc[j+1][2]), "+f"(acc[j+1][3])
                             : "r"(a0), "r"(a1), "r"(a2), "r"(a3), "r"(b2), "r"(b3));
            }
        }

        int idb0 = c0 + it * 128 + nhalf * 64 + (lane & 3) * 2;
        #pragma unroll
        for (int j = 0; j < 8; j++) {
            int idb = idb0 + j * 8;
            if (acc[j][0] > tv[0][3]) ins4p(tv[0], ti[0], acc[j][0], idb);
            if (acc[j][1] > tv[0][3]) ins4p(tv[0], ti[0], acc[j][1], idb + 1);
            if (acc[j][2] > tv[1][3]) ins4p(tv[1], ti[1], acc[j][2], idb);
            if (acc[j][3] > tv[1][3]) ins4p(tv[1], ti[1], acc[j][3], idb + 1);
        }
        __syncthreads();
    }

    #pragma unroll
    for (int step = 1; step <= 2; step <<= 1) {
        #pragma unroll
        for (int r = 0; r < 2; r++) {
            float ov[4]; int oi[4];
            #pragma unroll
            for (int s = 0; s < 4; s++) {
                ov[s] = __shfl_xor_sync(0xffffffffu, tv[r][s], step);
                oi[s] = __shfl_xor_sync(0xffffffffu, ti[r][s], step);
            }
            #pragma unroll
            for (int s = 0; s < 4; s++)
                if (ov[s] > tv[r][3]) ins4p(tv[r], ti[r], ov[s], oi[s]);
        }
    }

    if ((lane & 3) == 0) {
        int g = lane >> 2;
        int row0 = m0 + msub + g;
        int row1 = row0 + 8;
        int base0 = ((row0 * 8 + blockIdx.y) * 2 + nhalf) * 4;
        int base1 = ((row1 * 8 + blockIdx.y) * 2 + nhalf) * 4;
        #pragma unroll
        for (int s = 0; s < 4; s++) {
            pidx[base0 + s] = ti[0][s];
            pidx[base1 + s] = ti[1][s];
        }
    }
}

// ===== rescore 64 candidates/row (fp32) -> top-4 -> gather; vmem inline =====
__global__ void rescore_kernel(const float* __restrict__ Q, const float* __restrict__ KN,
                               const int* __restrict__ pidx, const float* __restrict__ AT,
                               const float* __restrict__ cvals, float* __restrict__ vc)
{
    int b = blockIdx.x;
    int t = threadIdx.x;          // 64 threads
    __shared__ float qrow[64];
    __shared__ float vals[64];
    __shared__ int   ids[64];
    __shared__ int   sidx[4];
    qrow[t] = Q[b * 64 + t];
    __syncthreads();
    int id = pidx[b * 64 + t];
    const float4* kr = (const float4*)(KN + (size_t)id * 64);
    const float4* q4 = (const float4*)qrow;
    float s = 0.f;
    #pragma unroll
    for (int j = 0; j < 16; j++) {
        float4 kv = kr[j];
        float4 qv = q4[j];
        s += qv.x * kv.x + qv.y * kv.y + qv.z * kv.z + qv.w * kv.w;
    }
    vals[t] = s; ids[t] = id;
    __syncthreads();
    if (t == 0) {
        float bv[4] = {NEG, NEG, NEG, NEG};
        int bi[4] = {0x7FFFFFFF, 0x7FFFFFFF, 0x7FFFFFFF, 0x7FFFFFFF};
        for (int j = 0; j < 64; j++) ins4(bv, bi, vals[j], ids[j]);
        sidx[0]=bi[0]; sidx[1]=bi[1]; sidx[2]=bi[2]; sidx[3]=bi[3];
    }
    __syncthreads();
    const float4* ar = (const float4*)(AT + (size_t)t * 64);
    float vm = 0.f;
    #pragma unroll
    for (int j = 0; j < 16; j++) {
        float4 av = ar[j];
        float4 qv = q4[j];
        vm += qv.x * av.x + qv.y * av.y + qv.z * av.z + qv.w * av.w;
    }
    float sum = cvals[(size_t)sidx[0] * 64 + t] + cvals[(size_t)sidx[1] * 64 + t]
              + cvals[(size_t)sidx[2] * 64 + t] + cvals[(size_t)sidx[3] * 64 + t];
    vc[b * 64 + t] = 0.5f * (vm + sum * 0.25f);
}

__global__ void cf_partial_kernel(const float* __restrict__ z1, const float* __restrict__ z2,
                                  const float* __restrict__ z, const float* __restrict__ vc,
                                  float* __restrict__ part)
{
    __shared__ float red[256];
    float s = 0.f;
    for (int i = blockIdx.x * 256 + threadIdx.x; i < BB * DD; i += 256 * 256) {
        float d = 0.5f * (z1[i] + z2[i]) - z[i] - vc[i];
        s += d * d;
    }
    red[threadIdx.x] = s;
    __syncthreads();
    for (int st = 128; st > 0; st >>= 1) {
        if (threadIdx.x < st) red[threadIdx.x] += red[threadIdx.x + st];
        __syncthreads();
    }
    if (threadIdx.x == 0) part[blockIdx.x] = red[0];
}

__global__ void cf_final_kernel(const float* __restrict__ part, float* __restrict__ out)
{
    __shared__ float red[256];
    red[threadIdx.x] = part[threadIdx.x];
    __syncthreads();
    for (int st = 128; st > 0; st >>= 1) {
        if (threadIdx.x < st) red[threadIdx.x] += red[threadIdx.x + st];
        __syncthreads();
    }
    if (threadIdx.x == 0) out[BB * DD] = red[0] * (1.0f / (float)(BB * DD));
}

extern "C" void kernel_launch(void* const* d_in, const int* in_sizes, int n_in,
                              void* d_out, int out_size)
{
    const float* z    = (const float*)d_in[0];
    const float* hot  = (const float*)d_in[2];
    const float* gap  = (const float*)d_in[3];
    const float* Wq   = (const float*)d_in[4];
    const float* bq   = (const float*)d_in[5];
    const float* Wf   = (const float*)d_in[6];
    const float* bf   = (const float*)d_in[7];
    const float* mem  = (const float*)d_in[8];
    const float* Wk   = (const float*)d_in[9];
    const float* Wo   = (const float*)d_in[10];
    const float* ck   = (const float*)d_in[11];
    const float* cvals= (const float*)d_in[12];
    const float* aemb = (const float*)d_in[13];
    const float* Wih  = (const float*)d_in[14];
    const float* Whh  = (const float*)d_in[15];
    const float* bih  = (const float*)d_in[16];
    const float* bhh  = (const float*)d_in[17];
    const float* h0   = (const float*)d_in[18];
    const float* Wo1  = (const float*)d_in[19];
    const float* bo1  = (const float*)d_in[20];
    const float* Wo2  = (const float*)d_in[21];
    const float* bo2  = (const float*)d_in[22];
    const int*   acts = (const int*)d_in[23];
    float* out = (float*)d_out;

    float* scr = nullptr;
    cudaGetSymbolAddress((void**)&scr, d_scr);
    __nv_bfloat16* Qh  = (__nv_bfloat16*)(scr + OFF_QH);
    __nv_bfloat16* KNh = (__nv_bfloat16*)(scr + OFF_KNH);

    // Fork a second stream so the independent GRU track overlaps the
    // screen/rescore track in the captured graph. Streams/events are created
    // per call (kernel_launch runs only a handful of times; none are device
    // memory allocations) and intentionally not destroyed while capture is live.
    cudaStream_t sB;
    cudaStreamCreateWithFlags(&sB, cudaStreamNonBlocking);
    cudaEvent_t e0, e1;
    cudaEventCreateWithFlags(&e0, cudaEventDisableTiming);
    cudaEventCreateWithFlags(&e1, cudaEventDisableTiming);

    cudaEventRecord(e0, 0);            // fork point (origin/default stream)
    cudaStreamWaitEvent(sB, e0, 0);

    // ---- Track A (origin stream): episodic recall ----
    normalize_rows_kernel<<<2048, 256>>>(ck, scr + OFF_KN, KNh);                       // 1
    gemm_kernel<<<dim3(64, 1), 256>>>(z, hot, Wq, bq, scr + OFF_Q, 64, 64, 0, Qh);     // 2
    prepA_kernel<<<8, 256>>>(mem, Wk, Wo, scr + OFF_APART);                            // 3
    mma_sims_kernel<<<dim3(64, 8), 256>>>(Qh, KNh, (int*)(scr + OFF_PIDX));            // 4 (ncu anchor)
    reduceAT_kernel<<<16, 256>>>(scr + OFF_APART, scr + OFF_AT);
    rescore_kernel<<<BB, 64>>>(scr + OFF_Q, scr + OFF_KN, (int*)(scr + OFF_PIDX),
                               scr + OFF_AT, cvals, scr + OFF_VC);
    fuse2_kernel<<<64, 256>>>(z, scr + OFF_VC, Wf, bf, gap, out);

    // ---- Track B (forked stream): GRU rollout -> z1, z2 ----
    gh0_kernel<<<48, 256, 0, sB>>>(h0, Whh, bhh, scr + OFF_GH0);
    gi_gemm_kernel<<<dim3(64, 6), 256, 0, sB>>>(z, aemb, acts, 0, Wih, bih, scr + OFF_GI, 384);
    gates0_kernel<<<2048, 256, 0, sB>>>(scr + OFF_GI, scr + OFF_GH0, h0, scr + OFF_H2A);
    gemm_kernel<<<dim3(64, 2), 256, 0, sB>>>(scr + OFF_H2A, nullptr, Wo1, bo1, scr + OFF_HID, 128, 128, 1, nullptr);
    gemm_kernel<<<dim3(64, 1), 256, 0, sB>>>(scr + OFF_HID, nullptr, Wo2, bo2, scr + OFF_Z1, 64, 128, 0, nullptr);
    gi_gemm_kernel<<<dim3(64, 6), 256, 0, sB>>>(scr + OFF_Z1, aemb, acts, 1, Wih, bih, scr + OFF_GI, 384);
    gemm_kernel<<<dim3(64, 6), 256, 0, sB>>>(scr + OFF_H2A, nullptr, Whh, bhh, scr + OFF_GH, 384, 128, 0, nullptr);
    gates_kernel<<<2048, 256, 0, sB>>>(scr + OFF_GI, scr + OFF_GH, scr + OFF_H2A, scr + OFF_H2B);
    gemm_kernel<<<dim3(64, 2), 256, 0, sB>>>(scr + OFF_H2B, nullptr, Wo1, bo1, scr + OFF_HID, 128, 128, 1, nullptr);
    gemm_kernel<<<dim3(64, 1), 256, 0, sB>>>(scr + OFF_HID, nullptr, Wo2, bo2, scr + OFF_Z2, 64, 128, 0, nullptr);
    cudaEventRecord(e1, sB);

    // ---- Join: cf loss needs z1/z2 (B) and vc (A) ----
    cudaStreamWaitEvent(0, e1, 0);
    cf_partial_kernel<<<256, 256>>>(scr + OFF_Z1, scr + OFF_Z2, z, scr + OFF_VC, scr + OFF_CFP);
    cf_final_kernel<<<1, 256>>>(scr + OFF_CFP, out);
}